// round 1
// baseline (speedup 1.0000x reference)
#include <cuda_runtime.h>
#include <math.h>

// ---------------- problem constants ----------------
#define LAYERS 8
#define D      1024
#define NH     16
#define HDIM   64
#define DFF    4096
#define VOCAB  50257
#define BATCH  2
#define TLEN   2048
#define MROWS  (BATCH*TLEN)   // 4096
#define EPS    1e-5f

// ---------------- scratch (static device globals; no allocs) ----------------
__device__ float g_h  [MROWS*(size_t)D];
__device__ float g_xn [MROWS*(size_t)D];
__device__ float g_q  [MROWS*(size_t)D];
__device__ float g_k  [MROWS*(size_t)D];
__device__ float g_v  [MROWS*(size_t)D];
__device__ float g_ctx[MROWS*(size_t)D];
__device__ float g_ff [MROWS*(size_t)DFF];
__device__ float g_hf [BATCH*D];

// ---------------- embed: h = W_emb[x] + pos ----------------
__global__ void __launch_bounds__(256) embed_kernel(const int* __restrict__ x,
    const float* __restrict__ wemb, const float* __restrict__ pos)
{
    int m = blockIdx.x;
    int tok = x[m];
    int t = m % TLEN;
    int c = threadIdx.x;  // 256 threads * float4 = 1024
    float4 e = ((const float4*)(wemb + (size_t)tok * D))[c];
    float4 p = ((const float4*)(pos  + (size_t)t   * D))[c];
    e.x += p.x; e.y += p.y; e.z += p.z; e.w += p.w;
    ((float4*)(g_h + (size_t)m * D))[c] = e;
}

// ---------------- layernorm (ddof=1, (std+eps) denom) ----------------
// in row = row0 + blockIdx.x*rstride ; out row = blockIdx.x
__global__ void __launch_bounds__(256) ln_kernel(const float* __restrict__ in,
    float* __restrict__ out, const float* __restrict__ sc, const float* __restrict__ sh,
    int row0, int rstride)
{
    int rin = row0 + blockIdx.x * rstride;
    int t = threadIdx.x;
    float4 v = ((const float4*)(in + (size_t)rin * D))[t];
    float s  = v.x + v.y + v.z + v.w;
    float ss = v.x*v.x + v.y*v.y + v.z*v.z + v.w*v.w;
    #pragma unroll
    for (int o = 16; o; o >>= 1) {
        s  += __shfl_xor_sync(0xffffffffu, s,  o);
        ss += __shfl_xor_sync(0xffffffffu, ss, o);
    }
    __shared__ float shs[8], shss[8];
    if ((t & 31) == 0) { shs[t >> 5] = s; shss[t >> 5] = ss; }
    __syncthreads();
    float tot = 0.f, tots = 0.f;
    #pragma unroll
    for (int i = 0; i < 8; i++) { tot += shs[i]; tots += shss[i]; }
    float mean = tot * (1.f / (float)D);
    float var  = (tots - (float)D * mean * mean) * (1.f / (float)(D - 1));
    var = fmaxf(var, 0.f);
    float inv = 1.f / (sqrtf(var) + EPS);
    float4 scv = ((const float4*)sc)[t];
    float4 shv = ((const float4*)sh)[t];
    float4 r;
    r.x = scv.x * (v.x - mean) * inv + shv.x;
    r.y = scv.y * (v.y - mean) * inv + shv.y;
    r.z = scv.z * (v.z - mean) * inv + shv.z;
    r.w = scv.w * (v.w - mean) * inv + shv.w;
    ((float4*)(out + (size_t)blockIdx.x * D))[t] = r;
}

// ---------------- gelu ----------------
__device__ __forceinline__ float gelu_f(float x) {
    const float c = 0.7978845608028654f;  // sqrt(2/pi)
    float x3 = x * x * x;
    return 0.5f * x * (1.f + tanhf(c * (x + 0.044715f * x3)));
}

// ---------------- GEMM: out[m][n] = sum_k A[m][k]*W[n][k] (+epilogue) ----------------
// mode 0: store ; mode 1: out = res + acc + bias ; mode 2: out = gelu(acc + bias)
#define BM 128
#define BN 64
#define BK 16

__global__ void __launch_bounds__(256) gemm_kernel(
    const float* __restrict__ A, const float* __restrict__ W,
    const float* __restrict__ bias, const float* __restrict__ res,
    float* __restrict__ out, int N, int K, int mode)
{
    __shared__ float As[BK][BM];
    __shared__ float Bs[BK][BN];
    int tid = threadIdx.x;
    int m0 = blockIdx.y * BM;
    int n0 = blockIdx.x * BN;

    int ar = tid >> 1;            // 0..127
    int ak = (tid & 1) * 8;       // 0 or 8
    int br = tid >> 2;            // 0..63
    int bk = (tid & 3) * 4;       // 0,4,8,12
    const float* Ap = A + (size_t)(m0 + ar) * K + ak;
    const float* Wp = W + (size_t)(n0 + br) * K + bk;

    int ty = tid >> 4;            // rows ty*8..+7
    int tx = tid & 15;            // cols tx*4..+3

    float acc[8][4];
    #pragma unroll
    for (int i = 0; i < 8; i++)
        #pragma unroll
        for (int j = 0; j < 4; j++) acc[i][j] = 0.f;

    for (int kt = 0; kt < K; kt += BK) {
        float4 a0 = *(const float4*)(Ap + kt);
        float4 a1 = *(const float4*)(Ap + kt + 4);
        float4 b0 = *(const float4*)(Wp + kt);
        As[ak + 0][ar] = a0.x; As[ak + 1][ar] = a0.y; As[ak + 2][ar] = a0.z; As[ak + 3][ar] = a0.w;
        As[ak + 4][ar] = a1.x; As[ak + 5][ar] = a1.y; As[ak + 6][ar] = a1.z; As[ak + 7][ar] = a1.w;
        Bs[bk + 0][br] = b0.x; Bs[bk + 1][br] = b0.y; Bs[bk + 2][br] = b0.z; Bs[bk + 3][br] = b0.w;
        __syncthreads();
        #pragma unroll
        for (int k = 0; k < BK; k++) {
            float4 av0 = *(const float4*)&As[k][ty * 8];
            float4 av1 = *(const float4*)&As[k][ty * 8 + 4];
            float4 bv  = *(const float4*)&Bs[k][tx * 4];
            float am[8] = {av0.x, av0.y, av0.z, av0.w, av1.x, av1.y, av1.z, av1.w};
            float bm[4] = {bv.x, bv.y, bv.z, bv.w};
            #pragma unroll
            for (int i = 0; i < 8; i++)
                #pragma unroll
                for (int j = 0; j < 4; j++)
                    acc[i][j] += am[i] * bm[j];
        }
        __syncthreads();
    }

    int mbase = m0 + ty * 8;
    int nbase = n0 + tx * 4;
    float4 bv = make_float4(0.f, 0.f, 0.f, 0.f);
    if (mode != 0) bv = *(const float4*)(bias + nbase);
    #pragma unroll
    for (int i = 0; i < 8; i++) {
        size_t off = (size_t)(mbase + i) * N + nbase;
        float4 r = make_float4(acc[i][0], acc[i][1], acc[i][2], acc[i][3]);
        if (mode == 1) {
            float4 rv = *(const float4*)(res + off);
            r.x += bv.x + rv.x; r.y += bv.y + rv.y;
            r.z += bv.z + rv.z; r.w += bv.w + rv.w;
        } else if (mode == 2) {
            r.x = gelu_f(r.x + bv.x); r.y = gelu_f(r.y + bv.y);
            r.z = gelu_f(r.z + bv.z); r.w = gelu_f(r.w + bv.w);
        }
        *(float4*)(out + off) = r;
    }
}

// ---------------- fused causal attention (flash-style, fp32) ----------------
// grid: (T/64, H, B), 128 threads. Q/K/V/O layout: [b*T + t][h*64 + d]
__global__ void __launch_bounds__(128) attn_kernel(
    const float* __restrict__ Q, const float* __restrict__ K,
    const float* __restrict__ V, float* __restrict__ O)
{
    extern __shared__ float smf[];
    float* Qs = smf;             // [64][64] kk-major: Qs[kk*64 + r]
    float* Ks = smf + 4096;      // [64][64] kk-major
    float* Vs = smf + 8192;      // [64][64] j-major: Vs[j*64 + d]
    float* Ps = smf + 12288;     // [64][65]
    float* rowm  = smf + 12288 + 64 * 65;
    float* rowl  = rowm + 64;
    float* rowsc = rowl + 64;

    int b = blockIdx.z, h = blockIdx.y;
    int q0 = blockIdx.x * 64;
    int tid = threadIdx.x;
    int col0 = h * HDIM;
    const float* Qb = Q + (size_t)(b * TLEN + q0) * D + col0;

    // load Q transposed: Qs[kk][r] (r varies over lanes -> conflict-free smem writes)
    {
        int r = tid & 63;
        int chalf = tid >> 6;
        #pragma unroll
        for (int pass = 0; pass < 8; pass++) {
            int c4 = (pass * 2 + chalf) * 4;
            float4 qv = *(const float4*)(Qb + (size_t)r * D + c4);
            Qs[(c4 + 0) * 64 + r] = qv.x; Qs[(c4 + 1) * 64 + r] = qv.y;
            Qs[(c4 + 2) * 64 + r] = qv.z; Qs[(c4 + 3) * 64 + r] = qv.w;
        }
    }
    if (tid < 64) { rowm[tid] = -1e30f; rowl[tid] = 0.f; }

    int tm = tid >> 3;   // rows tm*4..+3
    int tn = tid & 7;    // cols tn*8..+7
    float acc[4][8];
    #pragma unroll
    for (int i = 0; i < 4; i++)
        #pragma unroll
        for (int j = 0; j < 8; j++) acc[i][j] = 0.f;

    int nkb = (q0 >> 6) + 1;
    for (int kb = 0; kb < nkb; kb++) {
        int k0 = kb * 64;
        const float* Kb = K + (size_t)(b * TLEN + k0) * D + col0;
        const float* Vb = V + (size_t)(b * TLEN + k0) * D + col0;
        __syncthreads();   // previous iter's Ps/Vs reads done before overwrite
        {
            int r = tid & 63;
            int chalf = tid >> 6;
            #pragma unroll
            for (int pass = 0; pass < 8; pass++) {
                int c4 = (pass * 2 + chalf) * 4;
                float4 kv = *(const float4*)(Kb + (size_t)r * D + c4);
                Ks[(c4 + 0) * 64 + r] = kv.x; Ks[(c4 + 1) * 64 + r] = kv.y;
                Ks[(c4 + 2) * 64 + r] = kv.z; Ks[(c4 + 3) * 64 + r] = kv.w;
            }
            #pragma unroll
            for (int pass = 0; pass < 8; pass++) {
                int idx = tid + pass * 128;       // float4 index 0..1023
                int vr = idx >> 4;
                int vc = (idx & 15) * 4;
                float4 vv = *(const float4*)(Vb + (size_t)vr * D + vc);
                *(float4*)&Vs[vr * 64 + vc] = vv;
            }
        }
        __syncthreads();

        // S = Q K^T  (scaled by 1/8 below)
        float s[4][8];
        #pragma unroll
        for (int i = 0; i < 4; i++)
            #pragma unroll
            for (int j = 0; j < 8; j++) s[i][j] = 0.f;
        #pragma unroll 8
        for (int kk = 0; kk < 64; kk++) {
            float4 a   = *(const float4*)&Qs[kk * 64 + tm * 4];
            float4 b0v = *(const float4*)&Ks[kk * 64 + tn * 8];
            float4 b1v = *(const float4*)&Ks[kk * 64 + tn * 8 + 4];
            float am[4] = {a.x, a.y, a.z, a.w};
            float bm[8] = {b0v.x, b0v.y, b0v.z, b0v.w, b1v.x, b1v.y, b1v.z, b1v.w};
            #pragma unroll
            for (int i = 0; i < 4; i++)
                #pragma unroll
                for (int j = 0; j < 8; j++)
                    s[i][j] += am[i] * bm[j];
        }
        bool diag = (kb == nkb - 1);
        #pragma unroll
        for (int i = 0; i < 4; i++) {
            int gi = tm * 4 + i;
            #pragma unroll
            for (int j = 0; j < 8; j++) {
                int gj = tn * 8 + j;
                float val = s[i][j] * 0.125f;     // mask-then-scale == scale-then-mask here
                if (diag && gj > gi) val = -1e30f;
                Ps[gi * 65 + gj] = val;
            }
        }
        __syncthreads();

        // online softmax (one thread per row)
        if (tid < 64) {
            int r = tid;
            float mold = rowm[r];
            float mx = mold;
            for (int j = 0; j < 64; j++) mx = fmaxf(mx, Ps[r * 65 + j]);
            float scl = __expf(mold - mx);
            float sum = 0.f;
            for (int j = 0; j < 64; j++) {
                float p = __expf(Ps[r * 65 + j] - mx);
                Ps[r * 65 + j] = p;
                sum += p;
            }
            rowm[r] = mx;
            rowl[r] = rowl[r] * scl + sum;
            rowsc[r] = scl;
        }
        __syncthreads();

        // rescale accumulator + P@V
        float rs[4];
        #pragma unroll
        for (int i = 0; i < 4; i++) rs[i] = rowsc[tm * 4 + i];
        #pragma unroll
        for (int i = 0; i < 4; i++)
            #pragma unroll
            for (int j = 0; j < 8; j++) acc[i][j] *= rs[i];
        #pragma unroll 4
        for (int jj = 0; jj < 64; jj++) {
            float p0 = Ps[(tm * 4 + 0) * 65 + jj];
            float p1 = Ps[(tm * 4 + 1) * 65 + jj];
            float p2 = Ps[(tm * 4 + 2) * 65 + jj];
            float p3 = Ps[(tm * 4 + 3) * 65 + jj];
            float4 v0 = *(const float4*)&Vs[jj * 64 + tn * 8];
            float4 v1 = *(const float4*)&Vs[jj * 64 + tn * 8 + 4];
            float vm[8] = {v0.x, v0.y, v0.z, v0.w, v1.x, v1.y, v1.z, v1.w};
            #pragma unroll
            for (int c = 0; c < 8; c++) {
                acc[0][c] += p0 * vm[c];
                acc[1][c] += p1 * vm[c];
                acc[2][c] += p2 * vm[c];
                acc[3][c] += p3 * vm[c];
            }
        }
    }

    float invl[4];
    #pragma unroll
    for (int i = 0; i < 4; i++) invl[i] = 1.f / rowl[tm * 4 + i];
    #pragma unroll
    for (int i = 0; i < 4; i++) {
        size_t off = (size_t)(b * TLEN + q0 + tm * 4 + i) * D + col0 + tn * 8;
        float4 o0 = make_float4(acc[i][0] * invl[i], acc[i][1] * invl[i],
                                acc[i][2] * invl[i], acc[i][3] * invl[i]);
        float4 o1 = make_float4(acc[i][4] * invl[i], acc[i][5] * invl[i],
                                acc[i][6] * invl[i], acc[i][7] * invl[i]);
        *(float4*)(O + off)     = o0;
        *(float4*)(O + off + 4) = o1;
    }
}

// ---------------- last-token logits: out[b*V+n] = dot(hf[b], Wemb[n]) ----------------
__global__ void __launch_bounds__(256) logits_kernel(
    const float* __restrict__ hf, const float* __restrict__ wemb, float* __restrict__ out)
{
    __shared__ float h0[D], h1[D];
    int t = threadIdx.x;
    ((float4*)h0)[t] = ((const float4*)hf)[t];
    ((float4*)h1)[t] = ((const float4*)(hf + D))[t];
    __syncthreads();
    int warp = t >> 5, lane = t & 31;
    int n = blockIdx.x * 8 + warp;
    if (n >= VOCAB) return;
    const float4* w = (const float4*)(wemb + (size_t)n * D);
    float a0 = 0.f, a1 = 0.f;
    #pragma unroll
    for (int i = lane; i < D / 4; i += 32) {
        float4 wv = w[i];
        float4 x0 = ((float4*)h0)[i];
        float4 x1 = ((float4*)h1)[i];
        a0 += wv.x * x0.x + wv.y * x0.y + wv.z * x0.z + wv.w * x0.w;
        a1 += wv.x * x1.x + wv.y * x1.y + wv.z * x1.z + wv.w * x1.w;
    }
    #pragma unroll
    for (int o = 16; o; o >>= 1) {
        a0 += __shfl_xor_sync(0xffffffffu, a0, o);
        a1 += __shfl_xor_sync(0xffffffffu, a1, o);
    }
    if (lane == 0) {
        out[n] = a0;
        out[VOCAB + n] = a1;
    }
}

// ---------------- launch ----------------
extern "C" void kernel_launch(void* const* d_in, const int* in_sizes, int n_in,
                              void* d_out, int out_size)
{
    const int*   x       = (const int*)  d_in[0];
    const float* W_emb   = (const float*)d_in[1];
    const float* pos_emb = (const float*)d_in[2];
    const float* Wq      = (const float*)d_in[3];
    const float* Wk      = (const float*)d_in[4];
    const float* Wv      = (const float*)d_in[5];
    const float* Wo      = (const float*)d_in[6];
    const float* bo      = (const float*)d_in[7];
    const float* n1s     = (const float*)d_in[8];
    const float* n1b     = (const float*)d_in[9];
    const float* n2s     = (const float*)d_in[10];
    const float* n2b     = (const float*)d_in[11];
    const float* W1      = (const float*)d_in[12];
    const float* b1      = (const float*)d_in[13];
    const float* W2      = (const float*)d_in[14];
    const float* b2      = (const float*)d_in[15];
    const float* fs      = (const float*)d_in[16];
    const float* fb      = (const float*)d_in[17];
    float* out = (float*)d_out;

    float *h, *xn, *q, *k, *v, *ctx, *ff, *hf;
    cudaGetSymbolAddress((void**)&h,   g_h);
    cudaGetSymbolAddress((void**)&xn,  g_xn);
    cudaGetSymbolAddress((void**)&q,   g_q);
    cudaGetSymbolAddress((void**)&k,   g_k);
    cudaGetSymbolAddress((void**)&v,   g_v);
    cudaGetSymbolAddress((void**)&ctx, g_ctx);
    cudaGetSymbolAddress((void**)&ff,  g_ff);
    cudaGetSymbolAddress((void**)&hf,  g_hf);

    const int ATTN_SMEM = (12288 + 64 * 65 + 3 * 64) * 4;  // 66560 B
    cudaFuncSetAttribute(attn_kernel, cudaFuncAttributeMaxDynamicSharedMemorySize, ATTN_SMEM);

    embed_kernel<<<MROWS, 256>>>(x, W_emb, pos_emb);

    dim3 gD(D / BN, MROWS / BM);      // (16, 32)
    dim3 gF(DFF / BN, MROWS / BM);    // (64, 32)
    dim3 gA(TLEN / 64, NH, BATCH);

    for (int l = 0; l < LAYERS; l++) {
        size_t wo  = (size_t)l * D * D;
        size_t w1o = (size_t)l * DFF * D;
        size_t w2o = (size_t)l * D * DFF;
        ln_kernel<<<MROWS, 256>>>(h, xn, n1s + l * D, n1b + l * D, 0, 1);
        gemm_kernel<<<gD, 256>>>(xn, Wq + wo, nullptr, nullptr, q, D, D, 0);
        gemm_kernel<<<gD, 256>>>(xn, Wk + wo, nullptr, nullptr, k, D, D, 0);
        gemm_kernel<<<gD, 256>>>(xn, Wv + wo, nullptr, nullptr, v, D, D, 0);
        attn_kernel<<<gA, 128, ATTN_SMEM>>>(q, k, v, ctx);
        gemm_kernel<<<gD, 256>>>(ctx, Wo + wo, bo + l * D, h, h, D, D, 1);
        ln_kernel<<<MROWS, 256>>>(h, xn, n2s + l * D, n2b + l * D, 0, 1);
        gemm_kernel<<<gF, 256>>>(xn, W1 + w1o, b1 + (size_t)l * DFF, nullptr, ff, DFF, D, 2);
        gemm_kernel<<<gD, 256>>>(ff, W2 + w2o, b2 + l * D, h, h, D, DFF, 1);
    }

    ln_kernel<<<BATCH, 256>>>(h, hf, fs, fb, TLEN - 1, TLEN);
    logits_kernel<<<(VOCAB + 7) / 8, 256>>>(hf, W_emb, out);
}

// round 4
// speedup vs baseline: 3.2409x; 3.2409x over previous
#include <cuda_runtime.h>
#include <math.h>
#include <stdint.h>

// ---------------- problem constants ----------------
#define LAYERS 8
#define D      1024
#define NH     16
#define HDIM   64
#define DFF    4096
#define VOCAB  50257
#define BATCH  2
#define TLEN   2048
#define MROWS  (BATCH*TLEN)   // 4096
#define EPS    1e-5f

// ---------------- scratch (static device globals; no allocs) ----------------
__device__ float g_h  [MROWS*(size_t)D];
__device__ float g_xn [MROWS*(size_t)D];
__device__ float g_q  [MROWS*(size_t)D];
__device__ float g_k  [MROWS*(size_t)D];
__device__ float g_v  [MROWS*(size_t)D];
__device__ float g_ctx[MROWS*(size_t)D];
__device__ float g_ff [MROWS*(size_t)DFF];
__device__ float g_hf [BATCH*D];

// ---------------- embed ----------------
__global__ void __launch_bounds__(256) embed_kernel(const int* __restrict__ x,
    const float* __restrict__ wemb, const float* __restrict__ pos)
{
    int m = blockIdx.x;
    int tok = x[m];
    int t = m % TLEN;
    int c = threadIdx.x;
    float4 e = ((const float4*)(wemb + (size_t)tok * D))[c];
    float4 p = ((const float4*)(pos  + (size_t)t   * D))[c];
    e.x += p.x; e.y += p.y; e.z += p.z; e.w += p.w;
    ((float4*)(g_h + (size_t)m * D))[c] = e;
}

// ---------------- layernorm (ddof=1, (std+eps) denom) ----------------
__global__ void __launch_bounds__(256) ln_kernel(const float* __restrict__ in,
    float* __restrict__ out, const float* __restrict__ sc, const float* __restrict__ sh,
    int row0, int rstride)
{
    int rin = row0 + blockIdx.x * rstride;
    int t = threadIdx.x;
    float4 v = ((const float4*)(in + (size_t)rin * D))[t];
    float s  = v.x + v.y + v.z + v.w;
    float ss = v.x*v.x + v.y*v.y + v.z*v.z + v.w*v.w;
    #pragma unroll
    for (int o = 16; o; o >>= 1) {
        s  += __shfl_xor_sync(0xffffffffu, s,  o);
        ss += __shfl_xor_sync(0xffffffffu, ss, o);
    }
    __shared__ float shs[8], shss[8];
    if ((t & 31) == 0) { shs[t >> 5] = s; shss[t >> 5] = ss; }
    __syncthreads();
    float tot = 0.f, tots = 0.f;
    #pragma unroll
    for (int i = 0; i < 8; i++) { tot += shs[i]; tots += shss[i]; }
    float mean = tot * (1.f / (float)D);
    float var  = (tots - (float)D * mean * mean) * (1.f / (float)(D - 1));
    var = fmaxf(var, 0.f);
    float inv = 1.f / (sqrtf(var) + EPS);
    float4 scv = ((const float4*)sc)[t];
    float4 shv = ((const float4*)sh)[t];
    float4 r;
    r.x = scv.x * (v.x - mean) * inv + shv.x;
    r.y = scv.y * (v.y - mean) * inv + shv.y;
    r.z = scv.z * (v.z - mean) * inv + shv.z;
    r.w = scv.w * (v.w - mean) * inv + shv.w;
    ((float4*)(out + (size_t)blockIdx.x * D))[t] = r;
}

// ---------------- gelu ----------------
__device__ __forceinline__ float gelu_f(float x) {
    const float c = 0.7978845608028654f;
    float x3 = x * x * x;
    return 0.5f * x * (1.f + tanhf(c * (x + 0.044715f * x3)));
}

// ---------------- tf32 helpers ----------------
__device__ __forceinline__ uint32_t tf32r(float f) {
    uint32_t u;
    asm("cvt.rna.tf32.f32 %0, %1;" : "=r"(u) : "f"(f));
    return u;
}

__device__ __forceinline__ void mma_tf32(float* c, const uint32_t* a, const uint32_t* b) {
    asm volatile(
        "mma.sync.aligned.m16n8k8.row.col.f32.tf32.tf32.f32 "
        "{%0,%1,%2,%3}, {%4,%5,%6,%7}, {%8,%9}, {%0,%1,%2,%3};"
        : "+f"(c[0]), "+f"(c[1]), "+f"(c[2]), "+f"(c[3])
        : "r"(a[0]), "r"(a[1]), "r"(a[2]), "r"(a[3]), "r"(b[0]), "r"(b[1]));
}

__device__ __forceinline__ void ldsm4(uint32_t* r, uint32_t addr) {
    asm volatile("ldmatrix.sync.aligned.m8n8.x4.shared.b16 {%0,%1,%2,%3}, [%4];"
                 : "=r"(r[0]), "=r"(r[1]), "=r"(r[2]), "=r"(r[3]) : "r"(addr));
}

// ---------------- tf32 tensor-core GEMM ----------------
// out[m][n] = sum_k A[m][k]*W[n][k] (+epilogue). A:[M,K] W:[N,K] row-major fp32.
// mode 0: store ; 1: out = res + acc + bias ; 2: out = gelu(acc + bias)
#define TBM 128
#define TBN 128
#define TBK 16
#define TSTR 20   // smem row stride in u32 (16 + 4 pad -> 80B, conflict-free ldmatrix)

__global__ void __launch_bounds__(256, 2) gemm_tf32_kernel(
    const float* __restrict__ A, const float* __restrict__ W,
    const float* __restrict__ bias, const float* __restrict__ res,
    float* __restrict__ out, int N, int K, int mode)
{
    __shared__ uint32_t As[2][TBM * TSTR];
    __shared__ uint32_t Bs[2][TBN * TSTR];

    int tid = threadIdx.x;
    int lane = tid & 31;
    int warp = tid >> 5;
    int warp_m = warp >> 1;   // 0..3  -> 32 rows each
    int warp_n = warp & 1;    // 0..1  -> 64 cols each
    int m0 = blockIdx.y * TBM;
    int n0 = blockIdx.x * TBN;

    // global load: thread t -> row t>>1, cols (t&1)*8 .. +7 (two float4)
    int lr = tid >> 1;
    int lc = (tid & 1) * 8;
    const float* Ag = A + (size_t)(m0 + lr) * K + lc;
    const float* Wg = W + (size_t)(n0 + lr) * K + lc;
    int sto = lr * TSTR + lc;   // u32 offset in smem tile

    uint32_t as_base = (uint32_t)__cvta_generic_to_shared(&As[0][0]);
    uint32_t bs_base = (uint32_t)__cvta_generic_to_shared(&Bs[0][0]);

    // fragment smem byte offsets (lane-dependent, per k8 step add s*32)
    // A (x4): row = warp_m*32 + mt*16 + (lane&15), +16B if lane>=16
    uint32_t a_off0 = ((warp_m * 32 + (lane & 15)) * TSTR) * 4 + ((lane >> 4) * 16);
    // B (x4, two n8 tiles): row = warp_n*64 + pair*16 + ((lane>>4)&1)*8 + (lane&7), +16B if bit3
    uint32_t b_off0 = ((warp_n * 64 + ((lane >> 4) & 1) * 8 + (lane & 7)) * TSTR) * 4
                    + (((lane >> 3) & 1) * 16);

    float c[2][8][4];
    #pragma unroll
    for (int mt = 0; mt < 2; mt++)
        #pragma unroll
        for (int nt = 0; nt < 8; nt++)
            #pragma unroll
            for (int i = 0; i < 4; i++) c[mt][nt][i] = 0.f;

    float4 pa0 = *(const float4*)Ag;
    float4 pa1 = *(const float4*)(Ag + 4);
    float4 pb0 = *(const float4*)Wg;
    float4 pb1 = *(const float4*)(Wg + 4);

    int nk = K / TBK;
    for (int kt = 0; kt < nk; kt++) {
        int buf = kt & 1;
        // cvt.rna + store to smem
        {
            uint4 va = make_uint4(tf32r(pa0.x), tf32r(pa0.y), tf32r(pa0.z), tf32r(pa0.w));
            uint4 vb = make_uint4(tf32r(pa1.x), tf32r(pa1.y), tf32r(pa1.z), tf32r(pa1.w));
            *(uint4*)&As[buf][sto]     = va;
            *(uint4*)&As[buf][sto + 4] = vb;
            uint4 wa = make_uint4(tf32r(pb0.x), tf32r(pb0.y), tf32r(pb0.z), tf32r(pb0.w));
            uint4 wb = make_uint4(tf32r(pb1.x), tf32r(pb1.y), tf32r(pb1.z), tf32r(pb1.w));
            *(uint4*)&Bs[buf][sto]     = wa;
            *(uint4*)&Bs[buf][sto + 4] = wb;
        }
        __syncthreads();
        if (kt + 1 < nk) {
            Ag += TBK; Wg += TBK;
            pa0 = *(const float4*)Ag;
            pa1 = *(const float4*)(Ag + 4);
            pb0 = *(const float4*)Wg;
            pb1 = *(const float4*)(Wg + 4);
        }
        uint32_t abase = as_base + (uint32_t)(buf * TBM * TSTR * 4) + a_off0;
        uint32_t bbase = bs_base + (uint32_t)(buf * TBN * TSTR * 4) + b_off0;
        #pragma unroll
        for (int s = 0; s < 2; s++) {
            uint32_t af[2][4];
            uint32_t bf[4][4];
            #pragma unroll
            for (int mt = 0; mt < 2; mt++)
                ldsm4(af[mt], abase + mt * (16 * TSTR * 4) + s * 32);
            #pragma unroll
            for (int p = 0; p < 4; p++)
                ldsm4(bf[p], bbase + p * (16 * TSTR * 4) + s * 32);
            #pragma unroll
            for (int mt = 0; mt < 2; mt++)
                #pragma unroll
                for (int p = 0; p < 4; p++) {
                    mma_tf32(c[mt][2 * p],     af[mt], &bf[p][0]);
                    mma_tf32(c[mt][2 * p + 1], af[mt], &bf[p][2]);
                }
        }
        __syncthreads();
    }

    // epilogue: c0,c1 -> (row r, cols cb,cb+1), c2,c3 -> (row r+8)
    int rbase = m0 + warp_m * 32 + (lane >> 2);
    int cb0   = n0 + warp_n * 64 + (lane & 3) * 2;
    #pragma unroll
    for (int mt = 0; mt < 2; mt++) {
        #pragma unroll
        for (int nt = 0; nt < 8; nt++) {
            int col = cb0 + nt * 8;
            #pragma unroll
            for (int half = 0; half < 2; half++) {
                int row = rbase + mt * 16 + half * 8;
                float vx = c[mt][nt][half * 2];
                float vy = c[mt][nt][half * 2 + 1];
                size_t off = (size_t)row * N + col;
                if (mode == 1) {
                    float2 rv = *(const float2*)(res + off);
                    vx += bias[col] + rv.x;
                    vy += bias[col + 1] + rv.y;
                } else if (mode == 2) {
                    vx = gelu_f(vx + bias[col]);
                    vy = gelu_f(vy + bias[col + 1]);
                }
                *(float2*)(out + off) = make_float2(vx, vy);
            }
        }
    }
}

// ---------------- fused causal attention (flash-style, fp32) ----------------
__global__ void __launch_bounds__(128) attn_kernel(
    const float* __restrict__ Q, const float* __restrict__ K,
    const float* __restrict__ V, float* __restrict__ O)
{
    extern __shared__ float smf[];
    float* Qs = smf;             // [64][64] kk-major
    float* Ks = smf + 4096;
    float* Vs = smf + 8192;      // [j][d]
    float* Ps = smf + 12288;     // [64][65]
    float* rowm  = smf + 12288 + 64 * 65;
    float* rowl  = rowm + 64;
    float* rowsc = rowl + 64;

    int b = blockIdx.z, h = blockIdx.y;
    int q0 = blockIdx.x * 64;
    int tid = threadIdx.x;
    int col0 = h * HDIM;
    const float* Qb = Q + (size_t)(b * TLEN + q0) * D + col0;

    {
        int r = tid & 63;
        int chalf = tid >> 6;
        #pragma unroll
        for (int pass = 0; pass < 8; pass++) {
            int c4 = (pass * 2 + chalf) * 4;
            float4 qv = *(const float4*)(Qb + (size_t)r * D + c4);
            Qs[(c4 + 0) * 64 + r] = qv.x; Qs[(c4 + 1) * 64 + r] = qv.y;
            Qs[(c4 + 2) * 64 + r] = qv.z; Qs[(c4 + 3) * 64 + r] = qv.w;
        }
    }
    if (tid < 64) { rowm[tid] = -1e30f; rowl[tid] = 0.f; }

    int tm = tid >> 3;
    int tn = tid & 7;
    float acc[4][8];
    #pragma unroll
    for (int i = 0; i < 4; i++)
        #pragma unroll
        for (int j = 0; j < 8; j++) acc[i][j] = 0.f;

    int nkb = (q0 >> 6) + 1;
    for (int kb = 0; kb < nkb; kb++) {
        int k0 = kb * 64;
        const float* Kb = K + (size_t)(b * TLEN + k0) * D + col0;
        const float* Vb = V + (size_t)(b * TLEN + k0) * D + col0;
        __syncthreads();
        {
            int r = tid & 63;
            int chalf = tid >> 6;
            #pragma unroll
            for (int pass = 0; pass < 8; pass++) {
                int c4 = (pass * 2 + chalf) * 4;
                float4 kv = *(const float4*)(Kb + (size_t)r * D + c4);
                Ks[(c4 + 0) * 64 + r] = kv.x; Ks[(c4 + 1) * 64 + r] = kv.y;
                Ks[(c4 + 2) * 64 + r] = kv.z; Ks[(c4 + 3) * 64 + r] = kv.w;
            }
            #pragma unroll
            for (int pass = 0; pass < 8; pass++) {
                int idx = tid + pass * 128;
                int vr = idx >> 4;
                int vc = (idx & 15) * 4;
                float4 vv = *(const float4*)(Vb + (size_t)vr * D + vc);
                *(float4*)&Vs[vr * 64 + vc] = vv;
            }
        }
        __syncthreads();

        float s[4][8];
        #pragma unroll
        for (int i = 0; i < 4; i++)
            #pragma unroll
            for (int j = 0; j < 8; j++) s[i][j] = 0.f;
        #pragma unroll 8
        for (int kk = 0; kk < 64; kk++) {
            float4 a   = *(const float4*)&Qs[kk * 64 + tm * 4];
            float4 b0v = *(const float4*)&Ks[kk * 64 + tn * 8];
            float4 b1v = *(const float4*)&Ks[kk * 64 + tn * 8 + 4];
            float am[4] = {a.x, a.y, a.z, a.w};
            float bm[8] = {b0v.x, b0v.y, b0v.z, b0v.w, b1v.x, b1v.y, b1v.z, b1v.w};
            #pragma unroll
            for (int i = 0; i < 4; i++)
                #pragma unroll
                for (int j = 0; j < 8; j++)
                    s[i][j] += am[i] * bm[j];
        }
        bool diag = (kb == nkb - 1);
        #pragma unroll
        for (int i = 0; i < 4; i++) {
            int gi = tm * 4 + i;
            #pragma unroll
            for (int j = 0; j < 8; j++) {
                int gj = tn * 8 + j;
                float val = s[i][j] * 0.125f;
                if (diag && gj > gi) val = -1e30f;
                Ps[gi * 65 + gj] = val;
            }
        }
        __syncthreads();

        if (tid < 64) {
            int r = tid;
            float mold = rowm[r];
            float mx = mold;
            for (int j = 0; j < 64; j++) mx = fmaxf(mx, Ps[r * 65 + j]);
            float scl = __expf(mold - mx);
            float sum = 0.f;
            for (int j = 0; j < 64; j++) {
                float p = __expf(Ps[r * 65 + j] - mx);
                Ps[r * 65 + j] = p;
                sum += p;
            }
            rowm[r] = mx;
            rowl[r] = rowl[r] * scl + sum;
            rowsc[r] = scl;
        }
        __syncthreads();

        float rs[4];
        #pragma unroll
        for (int i = 0; i < 4; i++) rs[i] = rowsc[tm * 4 + i];
        #pragma unroll
        for (int i = 0; i < 4; i++)
            #pragma unroll
            for (int j = 0; j < 8; j++) acc[i][j] *= rs[i];
        #pragma unroll 4
        for (int jj = 0; jj < 64; jj++) {
            float p0 = Ps[(tm * 4 + 0) * 65 + jj];
            float p1 = Ps[(tm * 4 + 1) * 65 + jj];
            float p2 = Ps[(tm * 4 + 2) * 65 + jj];
            float p3 = Ps[(tm * 4 + 3) * 65 + jj];
            float4 v0 = *(const float4*)&Vs[jj * 64 + tn * 8];
            float4 v1 = *(const float4*)&Vs[jj * 64 + tn * 8 + 4];
            float vm[8] = {v0.x, v0.y, v0.z, v0.w, v1.x, v1.y, v1.z, v1.w};
            #pragma unroll
            for (int cc = 0; cc < 8; cc++) {
                acc[0][cc] += p0 * vm[cc];
                acc[1][cc] += p1 * vm[cc];
                acc[2][cc] += p2 * vm[cc];
                acc[3][cc] += p3 * vm[cc];
            }
        }
    }

    float invl[4];
    #pragma unroll
    for (int i = 0; i < 4; i++) invl[i] = 1.f / rowl[tm * 4 + i];
    #pragma unroll
    for (int i = 0; i < 4; i++) {
        size_t off = (size_t)(b * TLEN + q0 + tm * 4 + i) * D + col0 + tn * 8;
        float4 o0 = make_float4(acc[i][0] * invl[i], acc[i][1] * invl[i],
                                acc[i][2] * invl[i], acc[i][3] * invl[i]);
        float4 o1 = make_float4(acc[i][4] * invl[i], acc[i][5] * invl[i],
                                acc[i][6] * invl[i], acc[i][7] * invl[i]);
        *(float4*)(O + off)     = o0;
        *(float4*)(O + off + 4) = o1;
    }
}

// ---------------- last-token logits (fp32, memory-bound) ----------------
__global__ void __launch_bounds__(256) logits_kernel(
    const float* __restrict__ hf, const float* __restrict__ wemb, float* __restrict__ out)
{
    __shared__ float h0[D], h1[D];
    int t = threadIdx.x;
    ((float4*)h0)[t] = ((const float4*)hf)[t];
    ((float4*)h1)[t] = ((const float4*)(hf + D))[t];
    __syncthreads();
    int warp = t >> 5, lane = t & 31;
    int n = blockIdx.x * 8 + warp;
    if (n >= VOCAB) return;
    const float4* w = (const float4*)(wemb + (size_t)n * D);
    float a0 = 0.f, a1 = 0.f;
    #pragma unroll
    for (int i = lane; i < D / 4; i += 32) {
        float4 wv = w[i];
        float4 x0 = ((float4*)h0)[i];
        float4 x1 = ((float4*)h1)[i];
        a0 += wv.x * x0.x + wv.y * x0.y + wv.z * x0.z + wv.w * x0.w;
        a1 += wv.x * x1.x + wv.y * x1.y + wv.z * x1.z + wv.w * x1.w;
    }
    #pragma unroll
    for (int o = 16; o; o >>= 1) {
        a0 += __shfl_xor_sync(0xffffffffu, a0, o);
        a1 += __shfl_xor_sync(0xffffffffu, a1, o);
    }
    if (lane == 0) {
        out[n] = a0;
        out[VOCAB + n] = a1;
    }
}

// ---------------- launch ----------------
extern "C" void kernel_launch(void* const* d_in, const int* in_sizes, int n_in,
                              void* d_out, int out_size)
{
    const int*   x       = (const int*)  d_in[0];
    const float* W_emb   = (const float*)d_in[1];
    const float* pos_emb = (const float*)d_in[2];
    const float* Wq      = (const float*)d_in[3];
    const float* Wk      = (const float*)d_in[4];
    const float* Wv      = (const float*)d_in[5];
    const float* Wo      = (const float*)d_in[6];
    const float* bo      = (const float*)d_in[7];
    const float* n1s     = (const float*)d_in[8];
    const float* n1b     = (const float*)d_in[9];
    const float* n2s     = (const float*)d_in[10];
    const float* n2b     = (const float*)d_in[11];
    const float* W1      = (const float*)d_in[12];
    const float* b1      = (const float*)d_in[13];
    const float* W2      = (const float*)d_in[14];
    const float* b2      = (const float*)d_in[15];
    const float* fs      = (const float*)d_in[16];
    const float* fb      = (const float*)d_in[17];
    float* out = (float*)d_out;

    float *h, *xn, *q, *k, *v, *ctx, *ff, *hf;
    cudaGetSymbolAddress((void**)&h,   g_h);
    cudaGetSymbolAddress((void**)&xn,  g_xn);
    cudaGetSymbolAddress((void**)&q,   g_q);
    cudaGetSymbolAddress((void**)&k,   g_k);
    cudaGetSymbolAddress((void**)&v,   g_v);
    cudaGetSymbolAddress((void**)&ctx, g_ctx);
    cudaGetSymbolAddress((void**)&ff,  g_ff);
    cudaGetSymbolAddress((void**)&hf,  g_hf);

    const int ATTN_SMEM = (12288 + 64 * 65 + 3 * 64) * 4;  // 66560 B
    cudaFuncSetAttribute(attn_kernel, cudaFuncAttributeMaxDynamicSharedMemorySize, ATTN_SMEM);

    embed_kernel<<<MROWS, 256>>>(x, W_emb, pos_emb);

    dim3 gD(D / TBN, MROWS / TBM);      // (8, 32)
    dim3 gF(DFF / TBN, MROWS / TBM);    // (32, 32)
    dim3 gA(TLEN / 64, NH, BATCH);

    for (int l = 0; l < LAYERS; l++) {
        size_t wo  = (size_t)l * D * D;
        size_t w1o = (size_t)l * DFF * D;
        size_t w2o = (size_t)l * D * DFF;
        ln_kernel<<<MROWS, 256>>>(h, xn, n1s + l * D, n1b + l * D, 0, 1);
        gemm_tf32_kernel<<<gD, 256>>>(xn, Wq + wo, nullptr, nullptr, q, D, D, 0);
        gemm_tf32_kernel<<<gD, 256>>>(xn, Wk + wo, nullptr, nullptr, k, D, D, 0);
        gemm_tf32_kernel<<<gD, 256>>>(xn, Wv + wo, nullptr, nullptr, v, D, D, 0);
        attn_kernel<<<gA, 128, ATTN_SMEM>>>(q, k, v, ctx);
        gemm_tf32_kernel<<<gD, 256>>>(ctx, Wo + wo, bo + l * D, h, h, D, D, 1);
        ln_kernel<<<MROWS, 256>>>(h, xn, n2s + l * D, n2b + l * D, 0, 1);
        gemm_tf32_kernel<<<gF, 256>>>(xn, W1 + w1o, b1 + (size_t)l * DFF, nullptr, ff, DFF, D, 2);
        gemm_tf32_kernel<<<gD, 256>>>(ff, W2 + w2o, b2 + l * D, h, h, D, DFF, 1);
    }

    ln_kernel<<<BATCH, 256>>>(h, hf, fs, fb, TLEN - 1, TLEN);
    logits_kernel<<<(VOCAB + 7) / 8, 256>>>(hf, W_emb, out);
}

// round 6
// speedup vs baseline: 3.3005x; 1.0184x over previous
#include <cuda_runtime.h>
#include <cuda_bf16.h>
#include <math.h>
#include <stdint.h>

// ---------------- problem constants ----------------
#define LAYERS 8
#define D      1024
#define NH     16
#define HDIM   64
#define DFF    4096
#define VOCAB  50257
#define BATCH  2
#define TLEN   2048
#define MROWS  (BATCH*TLEN)   // 4096
#define EPS    1e-5f
#define QKV3   3072

// ---------------- scratch (static device globals; no allocs) ----------------
__device__ __nv_bfloat16 g_wqkv_h[LAYERS*(size_t)QKV3*D];
__device__ __nv_bfloat16 g_wqkv_l[LAYERS*(size_t)QKV3*D];
__device__ __nv_bfloat16 g_wo_h [LAYERS*(size_t)D*D];
__device__ __nv_bfloat16 g_wo_l [LAYERS*(size_t)D*D];
__device__ __nv_bfloat16 g_w1_h [LAYERS*(size_t)DFF*D];
__device__ __nv_bfloat16 g_w1_l [LAYERS*(size_t)DFF*D];
__device__ __nv_bfloat16 g_w2_h [LAYERS*(size_t)D*DFF];
__device__ __nv_bfloat16 g_w2_l [LAYERS*(size_t)D*DFF];
__device__ __nv_bfloat16 g_xn_h [MROWS*(size_t)D];
__device__ __nv_bfloat16 g_xn_l [MROWS*(size_t)D];
__device__ __nv_bfloat16 g_ctx_h[MROWS*(size_t)D];
__device__ __nv_bfloat16 g_ctx_l[MROWS*(size_t)D];
__device__ __nv_bfloat16 g_ff_h [MROWS*(size_t)DFF];
__device__ __nv_bfloat16 g_ff_l [MROWS*(size_t)DFF];
__device__ float g_qkv[MROWS*(size_t)QKV3];
__device__ float g_h  [MROWS*(size_t)D];
__device__ float g_hf [BATCH*D];

// ---------------- helpers ----------------
__device__ __forceinline__ void split2(float x, __nv_bfloat16& h, __nv_bfloat16& l) {
    h = __float2bfloat16(x);
    l = __float2bfloat16(x - __bfloat162float(h));
}

__device__ __forceinline__ float gelu_f(float x) {
    const float c = 0.7978845608028654f;
    float x3 = x * x * x;
    return 0.5f * x * (1.f + tanhf(c * (x + 0.044715f * x3)));
}

__device__ __forceinline__ void ldsm4(uint32_t* r, uint32_t addr) {
    asm volatile("ldmatrix.sync.aligned.m8n8.x4.shared.b16 {%0,%1,%2,%3}, [%4];"
                 : "=r"(r[0]), "=r"(r[1]), "=r"(r[2]), "=r"(r[3]) : "r"(addr));
}

__device__ __forceinline__ void mma_bf16(float* c, const uint32_t* a, const uint32_t* b) {
    asm volatile(
        "mma.sync.aligned.m16n8k16.row.col.f32.bf16.bf16.f32 "
        "{%0,%1,%2,%3}, {%4,%5,%6,%7}, {%8,%9}, {%0,%1,%2,%3};"
        : "+f"(c[0]), "+f"(c[1]), "+f"(c[2]), "+f"(c[3])
        : "r"(a[0]), "r"(a[1]), "r"(a[2]), "r"(a[3]), "r"(b[0]), "r"(b[1]));
}

__device__ __forceinline__ void cpa16(uint32_t s, const void* g) {
    asm volatile("cp.async.cg.shared.global [%0], [%1], 16;" :: "r"(s), "l"(g));
}
__device__ __forceinline__ void cp_commit() { asm volatile("cp.async.commit_group;"); }
__device__ __forceinline__ void cp_wait1()  { asm volatile("cp.async.wait_group 1;"); }
__device__ __forceinline__ void cp_wait0()  { asm volatile("cp.async.wait_group 0;"); }

// ---------------- weight split/pack kernels ----------------
__global__ void __launch_bounds__(256) split_w_kernel(const float* __restrict__ src,
    __nv_bfloat16* __restrict__ dh, __nv_bfloat16* __restrict__ dl)
{
    size_t i8 = ((size_t)blockIdx.x * 256 + threadIdx.x) * 8;
    float4 v0 = *(const float4*)(src + i8);
    float4 v1 = *(const float4*)(src + i8 + 4);
    __align__(16) __nv_bfloat16 h[8], l[8];
    split2(v0.x, h[0], l[0]); split2(v0.y, h[1], l[1]);
    split2(v0.z, h[2], l[2]); split2(v0.w, h[3], l[3]);
    split2(v1.x, h[4], l[4]); split2(v1.y, h[5], l[5]);
    split2(v1.z, h[6], l[6]); split2(v1.w, h[7], l[7]);
    *(uint4*)(dh + i8) = *(uint4*)h;
    *(uint4*)(dl + i8) = *(uint4*)l;
}

__global__ void __launch_bounds__(256) pack_qkv_kernel(const float* __restrict__ Wq,
    const float* __restrict__ Wk, const float* __restrict__ Wv)
{
    size_t i8 = ((size_t)blockIdx.x * 256 + threadIdx.x) * 8;
    size_t per_l = (size_t)QKV3 * D;
    int l = (int)(i8 / per_l);
    size_t rem = i8 % per_l;
    int n = (int)(rem / D);
    int k = (int)(rem % D);
    const float* src;
    if (n < D)          src = Wq + ((size_t)l * D + n) * D + k;
    else if (n < 2 * D) src = Wk + ((size_t)l * D + (n - D)) * D + k;
    else                src = Wv + ((size_t)l * D + (n - 2 * D)) * D + k;
    float4 v0 = *(const float4*)src;
    float4 v1 = *(const float4*)(src + 4);
    __align__(16) __nv_bfloat16 h[8], lo[8];
    split2(v0.x, h[0], lo[0]); split2(v0.y, h[1], lo[1]);
    split2(v0.z, h[2], lo[2]); split2(v0.w, h[3], lo[3]);
    split2(v1.x, h[4], lo[4]); split2(v1.y, h[5], lo[5]);
    split2(v1.z, h[6], lo[6]); split2(v1.w, h[7], lo[7]);
    *(uint4*)(g_wqkv_h + i8) = *(uint4*)h;
    *(uint4*)(g_wqkv_l + i8) = *(uint4*)lo;
}

// ---------------- embed ----------------
__global__ void __launch_bounds__(256) embed_kernel(const int* __restrict__ x,
    const float* __restrict__ wemb, const float* __restrict__ pos)
{
    int m = blockIdx.x;
    int tok = x[m];
    int t = m % TLEN;
    int c = threadIdx.x;
    float4 e = ((const float4*)(wemb + (size_t)tok * D))[c];
    float4 p = ((const float4*)(pos  + (size_t)t   * D))[c];
    e.x += p.x; e.y += p.y; e.z += p.z; e.w += p.w;
    ((float4*)(g_h + (size_t)m * D))[c] = e;
}

// ---------------- layernorm -> split bf16 planes ----------------
__global__ void __launch_bounds__(256) ln_split_kernel(const float* __restrict__ in,
    __nv_bfloat16* __restrict__ oh, __nv_bfloat16* __restrict__ ol,
    const float* __restrict__ sc, const float* __restrict__ sh)
{
    int row = blockIdx.x;
    int t = threadIdx.x;
    float4 v = ((const float4*)(in + (size_t)row * D))[t];
    float s  = v.x + v.y + v.z + v.w;
    float ss = v.x*v.x + v.y*v.y + v.z*v.z + v.w*v.w;
    #pragma unroll
    for (int o = 16; o; o >>= 1) {
        s  += __shfl_xor_sync(0xffffffffu, s,  o);
        ss += __shfl_xor_sync(0xffffffffu, ss, o);
    }
    __shared__ float shs[8], shss[8];
    if ((t & 31) == 0) { shs[t >> 5] = s; shss[t >> 5] = ss; }
    __syncthreads();
    float tot = 0.f, tots = 0.f;
    #pragma unroll
    for (int i = 0; i < 8; i++) { tot += shs[i]; tots += shss[i]; }
    float mean = tot * (1.f / (float)D);
    float var  = (tots - (float)D * mean * mean) * (1.f / (float)(D - 1));
    var = fmaxf(var, 0.f);
    float inv = 1.f / (sqrtf(var) + EPS);
    float4 scv = ((const float4*)sc)[t];
    float4 shv = ((const float4*)sh)[t];
    float r0 = scv.x * (v.x - mean) * inv + shv.x;
    float r1 = scv.y * (v.y - mean) * inv + shv.y;
    float r2 = scv.z * (v.z - mean) * inv + shv.z;
    float r3 = scv.w * (v.w - mean) * inv + shv.w;
    __align__(8) __nv_bfloat16 h[4], l[4];
    split2(r0, h[0], l[0]); split2(r1, h[1], l[1]);
    split2(r2, h[2], l[2]); split2(r3, h[3], l[3]);
    *(uint2*)(oh + (size_t)row * D + t * 4) = *(uint2*)h;
    *(uint2*)(ol + (size_t)row * D + t * 4) = *(uint2*)l;
}

// ---------------- layernorm fp32 out (final) ----------------
__global__ void __launch_bounds__(256) ln_kernel(const float* __restrict__ in,
    float* __restrict__ out, const float* __restrict__ sc, const float* __restrict__ sh,
    int row0, int rstride)
{
    int rin = row0 + blockIdx.x * rstride;
    int t = threadIdx.x;
    float4 v = ((const float4*)(in + (size_t)rin * D))[t];
    float s  = v.x + v.y + v.z + v.w;
    float ss = v.x*v.x + v.y*v.y + v.z*v.z + v.w*v.w;
    #pragma unroll
    for (int o = 16; o; o >>= 1) {
        s  += __shfl_xor_sync(0xffffffffu, s,  o);
        ss += __shfl_xor_sync(0xffffffffu, ss, o);
    }
    __shared__ float shs[8], shss[8];
    if ((t & 31) == 0) { shs[t >> 5] = s; shss[t >> 5] = ss; }
    __syncthreads();
    float tot = 0.f, tots = 0.f;
    #pragma unroll
    for (int i = 0; i < 8; i++) { tot += shs[i]; tots += shss[i]; }
    float mean = tot * (1.f / (float)D);
    float var  = (tots - (float)D * mean * mean) * (1.f / (float)(D - 1));
    var = fmaxf(var, 0.f);
    float inv = 1.f / (sqrtf(var) + EPS);
    float4 scv = ((const float4*)sc)[t];
    float4 shv = ((const float4*)sh)[t];
    float4 r;
    r.x = scv.x * (v.x - mean) * inv + shv.x;
    r.y = scv.y * (v.y - mean) * inv + shv.y;
    r.z = scv.z * (v.z - mean) * inv + shv.z;
    r.w = scv.w * (v.w - mean) * inv + shv.w;
    ((float4*)(out + (size_t)blockIdx.x * D))[t] = r;
}

// ---------------- split-bf16 tensor-core GEMM ----------------
// out[m][n] = sum_k A[m][k]*W[n][k], A = Ah+Al, W = Wh+Wl (3 mma combos, lo*lo dropped)
// mode 0: store fp32 ; 1: out = res + acc + bias (fp32) ; 2: oh/ol = split(gelu(acc+bias))
// CTA tile 128x128, K-stage 32, double-buffered cp.async.
#define SROW  40                   // smem row stride (bf16 elements): 32 + 8 pad = 80B
#define PLANE (128*SROW)           // 5120 els per plane
#define PLB   (PLANE*2)            // plane bytes = 10240
#define STGB  (4*PLB)              // stage bytes = 40960

__global__ void __launch_bounds__(256, 2) gemm_bf16s_kernel(
    const __nv_bfloat16* __restrict__ Ah, const __nv_bfloat16* __restrict__ Al,
    const __nv_bfloat16* __restrict__ Wh, const __nv_bfloat16* __restrict__ Wl,
    const float* __restrict__ bias, const float* __restrict__ res,
    float* __restrict__ out,
    __nv_bfloat16* __restrict__ oh, __nv_bfloat16* __restrict__ ol,
    int N, int K, int mode)
{
    extern __shared__ __align__(16) char smraw[];
    uint32_t smb = (uint32_t)__cvta_generic_to_shared(smraw);

    int tid = threadIdx.x, lane = tid & 31, warp = tid >> 5;
    int warp_m = warp >> 1;     // 0..3 -> 32 rows
    int warp_n = warp & 1;      // 0..1 -> 64 cols
    int m0 = blockIdx.y * 128;
    int n0 = blockIdx.x * 128;

    // cp.async: per plane, thread handles rows lr and lr+64 at col lc (8 els = 16B)
    int lr = tid >> 2;
    int lc = (tid & 3) * 8;
    const __nv_bfloat16* gAh = Ah + (size_t)(m0 + lr) * K + lc;
    const __nv_bfloat16* gAl = Al + (size_t)(m0 + lr) * K + lc;
    const __nv_bfloat16* gBh = Wh + (size_t)(n0 + lr) * K + lc;
    const __nv_bfloat16* gBl = Wl + (size_t)(n0 + lr) * K + lc;
    size_t rstep = (size_t)64 * K;
    uint32_t sdst = smb + (uint32_t)(lr * SROW + lc) * 2;

    // ldmatrix lane offsets (bytes within a plane)
    uint32_t a_off = (uint32_t)((warp_m * 32 + (lane & 15)) * SROW) * 2 + (lane >> 4) * 16;
    uint32_t b_off = (uint32_t)((warp_n * 64 + ((lane >> 4) & 1) * 8 + (lane & 7)) * SROW) * 2
                   + ((lane >> 3) & 1) * 16;

    float c[2][8][4];
    #pragma unroll
    for (int mt = 0; mt < 2; mt++)
        #pragma unroll
        for (int nt = 0; nt < 8; nt++)
            #pragma unroll
            for (int i = 0; i < 4; i++) c[mt][nt][i] = 0.f;

    int nk = K / 32;

    // prologue: stage 0
    {
        uint32_t sb = sdst;
        cpa16(sb,             gAh);          cpa16(sb + 64 * SROW * 2,             gAh + rstep);
        cpa16(sb + PLB,       gAl);          cpa16(sb + PLB + 64 * SROW * 2,       gAl + rstep);
        cpa16(sb + 2 * PLB,   gBh);          cpa16(sb + 2 * PLB + 64 * SROW * 2,   gBh + rstep);
        cpa16(sb + 3 * PLB,   gBl);          cpa16(sb + 3 * PLB + 64 * SROW * 2,   gBl + rstep);
        cp_commit();
    }

    for (int kt = 0; kt < nk; kt++) {
        int buf = kt & 1;
        if (kt + 1 < nk) {
            uint32_t sb = sdst + (uint32_t)((buf ^ 1) * STGB);
            int ko = (kt + 1) * 32;
            cpa16(sb,           gAh + ko);        cpa16(sb + 64 * SROW * 2,           gAh + ko + rstep);
            cpa16(sb + PLB,     gAl + ko);        cpa16(sb + PLB + 64 * SROW * 2,     gAl + ko + rstep);
            cpa16(sb + 2 * PLB, gBh + ko);        cpa16(sb + 2 * PLB + 64 * SROW * 2, gBh + ko + rstep);
            cpa16(sb + 3 * PLB, gBl + ko);        cpa16(sb + 3 * PLB + 64 * SROW * 2, gBl + ko + rstep);
            cp_commit();
            cp_wait1();
        } else {
            cp_wait0();
        }
        __syncthreads();

        uint32_t base = smb + (uint32_t)(buf * STGB);
        #pragma unroll
        for (int s = 0; s < 2; s++) {
            uint32_t ah[2][4], al[2][4];
            ldsm4(ah[0], base + a_off + s * 32);
            ldsm4(ah[1], base + a_off + 16 * SROW * 2 + s * 32);
            ldsm4(al[0], base + PLB + a_off + s * 32);
            ldsm4(al[1], base + PLB + a_off + 16 * SROW * 2 + s * 32);
            // B hi plane: hi*hi and lo*hi
            #pragma unroll
            for (int p2 = 0; p2 < 4; p2++) {
                uint32_t bh[4];
                ldsm4(bh, base + 2 * PLB + b_off + p2 * (16 * SROW * 2) + s * 32);
                #pragma unroll
                for (int mt = 0; mt < 2; mt++) {
                    mma_bf16(c[mt][2 * p2],     ah[mt], &bh[0]);
                    mma_bf16(c[mt][2 * p2 + 1], ah[mt], &bh[2]);
                    mma_bf16(c[mt][2 * p2],     al[mt], &bh[0]);
                    mma_bf16(c[mt][2 * p2 + 1], al[mt], &bh[2]);
                }
            }
            // B lo plane: hi*lo
            #pragma unroll
            for (int p2 = 0; p2 < 4; p2++) {
                uint32_t bl[4];
                ldsm4(bl, base + 3 * PLB + b_off + p2 * (16 * SROW * 2) + s * 32);
                #pragma unroll
                for (int mt = 0; mt < 2; mt++) {
                    mma_bf16(c[mt][2 * p2],     ah[mt], &bl[0]);
                    mma_bf16(c[mt][2 * p2 + 1], ah[mt], &bl[2]);
                }
            }
        }
        __syncthreads();
    }

    // epilogue: c[mt][nt][0,1] -> row rbase+mt*16, cols cb0+nt*8 (+1); [2,3] -> row +8
    int rbase = m0 + warp_m * 32 + (lane >> 2);
    int cb0   = n0 + warp_n * 64 + (lane & 3) * 2;
    #pragma unroll
    for (int mt = 0; mt < 2; mt++) {
        #pragma unroll
        for (int nt = 0; nt < 8; nt++) {
            int col = cb0 + nt * 8;
            #pragma unroll
            for (int half = 0; half < 2; half++) {
                int row = rbase + mt * 16 + half * 8;
                float vx = c[mt][nt][half * 2];
                float vy = c[mt][nt][half * 2 + 1];
                size_t off = (size_t)row * N + col;
                if (mode == 0) {
                    *(float2*)(out + off) = make_float2(vx, vy);
                } else if (mode == 1) {
                    float2 rv = *(const float2*)(res + off);
                    vx += bias[col] + rv.x;
                    vy += bias[col + 1] + rv.y;
                    *(float2*)(out + off) = make_float2(vx, vy);
                } else {
                    vx = gelu_f(vx + bias[col]);
                    vy = gelu_f(vy + bias[col + 1]);
                    __nv_bfloat16 hx, lx, hy, ly;
                    split2(vx, hx, lx); split2(vy, hy, ly);
                    __nv_bfloat162 hp; hp.x = hx; hp.y = hy;
                    __nv_bfloat162 lp; lp.x = lx; lp.y = ly;
                    *(__nv_bfloat162*)(oh + off) = hp;
                    *(__nv_bfloat162*)(ol + off) = lp;
                }
            }
        }
    }
}

// ---------------- fused causal attention (flash-style, fp32) ----------------
// Q/K/V packed: qkv[m][0:1024]=q, [1024:2048]=k, [2048:3072]=v. ctx out: split bf16.
__global__ void __launch_bounds__(128) attn_kernel(
    const float* __restrict__ QKV,
    __nv_bfloat16* __restrict__ Oh, __nv_bfloat16* __restrict__ Ol)
{
    extern __shared__ float smf[];
    float* Qs = smf;             // [64][64] kk-major
    float* Ks = smf + 4096;
    float* Vs = smf + 8192;      // [j][d]
    float* Ps = smf + 12288;     // [64][65]
    float* rowm  = smf + 12288 + 64 * 65;
    float* rowl  = rowm + 64;
    float* rowsc = rowl + 64;

    int b = blockIdx.z, h = blockIdx.y;
    int q0 = blockIdx.x * 64;
    int tid = threadIdx.x;
    int col0 = h * HDIM;
    const float* Qb = QKV + (size_t)(b * TLEN + q0) * QKV3 + col0;

    {
        int r = tid & 63;
        int chalf = tid >> 6;
        #pragma unroll
        for (int pass = 0; pass < 8; pass++) {
            int c4 = (pass * 2 + chalf) * 4;
            float4 qv = *(const float4*)(Qb + (size_t)r * QKV3 + c4);
            Qs[(c4 + 0) * 64 + r] = qv.x; Qs[(c4 + 1) * 64 + r] = qv.y;
            Qs[(c4 + 2) * 64 + r] = qv.z; Qs[(c4 + 3) * 64 + r] = qv.w;
        }
    }
    if (tid < 64) { rowm[tid] = -1e30f; rowl[tid] = 0.f; }

    int tm = tid >> 3;
    int tn = tid & 7;
    float acc[4][8];
    #pragma unroll
    for (int i = 0; i < 4; i++)
        #pragma unroll
        for (int j = 0; j < 8; j++) acc[i][j] = 0.f;

    int nkb = (q0 >> 6) + 1;
    for (int kb = 0; kb < nkb; kb++) {
        int k0 = kb * 64;
        const float* Kb = QKV + (size_t)(b * TLEN + k0) * QKV3 + D + col0;
        const float* Vb = QKV + (size_t)(b * TLEN + k0) * QKV3 + 2 * D + col0;
        __syncthreads();
        {
            int r = tid & 63;
            int chalf = tid >> 6;
            #pragma unroll
            for (int pass = 0; pass < 8; pass++) {
                int c4 = (pass * 2 + chalf) * 4;
                float4 kv = *(const float4*)(Kb + (size_t)r * QKV3 + c4);
                Ks[(c4 + 0) * 64 + r] = kv.x; Ks[(c4 + 1) * 64 + r] = kv.y;
                Ks[(c4 + 2) * 64 + r] = kv.z; Ks[(c4 + 3) * 64 + r] = kv.w;
            }
            #pragma unroll
            for (int pass = 0; pass < 8; pass++) {
                int idx = tid + pass * 128;
                int vr = idx >> 4;
                int vc = (idx & 15) * 4;
                float4 vv = *(const float4*)(Vb + (size_t)vr * QKV3 + vc);
                *(float4*)&Vs[vr * 64 + vc] = vv;
            }
        }
        __syncthreads();

        float s[4][8];
        #pragma unroll
        for (int i = 0; i < 4; i++)
            #pragma unroll
            for (int j = 0; j < 8; j++) s[i][j] = 0.f;
        #pragma unroll 8
        for (int kk = 0; kk < 64; kk++) {
            float4 a   = *(const float4*)&Qs[kk * 64 + tm * 4];
            float4 b0v = *(const float4*)&Ks[kk * 64 + tn * 8];
            float4 b1v = *(const float4*)&Ks[kk * 64 + tn * 8 + 4];
            float am[4] = {a.x, a.y, a.z, a.w};
            float bm[8] = {b0v.x, b0v.y, b0v.z, b0v.w, b1v.x, b1v.y, b1v.z, b1v.w};
            #pragma unroll
            for (int i = 0; i < 4; i++)
                #pragma unroll
                for (int j = 0; j < 8; j++)
                    s[i][j] += am[i] * bm[j];
        }
        bool diag = (kb == nkb - 1);
        #pragma unroll
        for (int i = 0; i < 4; i++) {
            int gi = tm * 4 + i;
            #pragma unroll
            for (int j = 0; j < 8; j++) {
                int gj = tn * 8 + j;
                float val = s[i][j] * 0.125f;
                if (diag && gj > gi) val = -1e30f;
                Ps[gi * 65 + gj] = val;
            }
        }
        __syncthreads();

        if (tid < 64) {
            int r = tid;
            float mold = rowm[r];
            float mx = mold;
            for (int j = 0; j < 64; j++) mx = fmaxf(mx, Ps[r * 65 + j]);
            float scl = __expf(mold - mx);
            float sum = 0.f;
            for (int j = 0; j < 64; j++) {
                float p = __expf(Ps[r * 65 + j] - mx);
                Ps[r * 65 + j] = p;
                sum += p;
            }
            rowm[r] = mx;
            rowl[r] = rowl[r] * scl + sum;
            rowsc[r] = scl;
        }
        __syncthreads();

        float rs[4];
        #pragma unroll
        for (int i = 0; i < 4; i++) rs[i] = rowsc[tm * 4 + i];
        #pragma unroll
        for (int i = 0; i < 4; i++)
            #pragma unroll
            for (int j = 0; j < 8; j++) acc[i][j] *= rs[i];
        #pragma unroll 4
        for (int jj = 0; jj < 64; jj++) {
            float p0 = Ps[(tm * 4 + 0) * 65 + jj];
            float p1 = Ps[(tm * 4 + 1) * 65 + jj];
            float p2 = Ps[(tm * 4 + 2) * 65 + jj];
            float p3 = Ps[(tm * 4 + 3) * 65 + jj];
            float4 v0 = *(const float4*)&Vs[jj * 64 + tn * 8];
            float4 v1 = *(const float4*)&Vs[jj * 64 + tn * 8 + 4];
            float vm[8] = {v0.x, v0.y, v0.z, v0.w, v1.x, v1.y, v1.z, v1.w};
            #pragma unroll
            for (int cc = 0; cc < 8; cc++) {
                acc[0][cc] += p0 * vm[cc];
                acc[1][cc] += p1 * vm[cc];
                acc[2][cc] += p2 * vm[cc];
                acc[3][cc] += p3 * vm[cc];
            }
        }
    }

    float invl[4];
    #pragma unroll
    for (int i = 0; i < 4; i++) invl[i] = 1.f / rowl[tm * 4 + i];
    #pragma unroll
    for (int i = 0; i < 4; i++) {
        size_t off = (size_t)(b * TLEN + q0 + tm * 4 + i) * D + col0 + tn * 8;
        __align__(16) __nv_bfloat16 hv[8], lv[8];
        #pragma unroll
        for (int cc = 0; cc < 8; cc++) {
            float o = acc[i][cc] * invl[i];
            split2(o, hv[cc], lv[cc]);
        }
        *(uint4*)(Oh + off) = *(uint4*)hv;
        *(uint4*)(Ol + off) = *(uint4*)lv;
    }
}

// ---------------- last-token logits ----------------
__global__ void __launch_bounds__(256) logits_kernel(
    const float* __restrict__ hf, const float* __restrict__ wemb, float* __restrict__ out)
{
    __shared__ float h0[D], h1[D];
    int t = threadIdx.x;
    ((float4*)h0)[t] = ((const float4*)hf)[t];
    ((float4*)h1)[t] = ((const float4*)(hf + D))[t];
    __syncthreads();
    int warp = t >> 5, lane = t & 31;
    int n = blockIdx.x * 8 + warp;
    if (n >= VOCAB) return;
    const float4* w = (const float4*)(wemb + (size_t)n * D);
    float a0 = 0.f, a1 = 0.f;
    #pragma unroll
    for (int i = lane; i < D / 4; i += 32) {
        float4 wv = w[i];
        float4 x0 = ((float4*)h0)[i];
        float4 x1 = ((float4*)h1)[i];
        a0 += wv.x * x0.x + wv.y * x0.y + wv.z * x0.z + wv.w * x0.w;
        a1 += wv.x * x1.x + wv.y * x1.y + wv.z * x1.z + wv.w * x1.w;
    }
    #pragma unroll
    for (int o = 16; o; o >>= 1) {
        a0 += __shfl_xor_sync(0xffffffffu, a0, o);
        a1 += __shfl_xor_sync(0xffffffffu, a1, o);
    }
    if (lane == 0) {
        out[n] = a0;
        out[VOCAB + n] = a1;
    }
}

// ---------------- launch ----------------
extern "C" void kernel_launch(void* const* d_in, const int* in_sizes, int n_in,
                              void* d_out, int out_size)
{
    const int*   x       = (const int*)  d_in[0];
    const float* W_emb   = (const float*)d_in[1];
    const float* pos_emb = (const float*)d_in[2];
    const float* Wq      = (const float*)d_in[3];
    const float* Wk      = (const float*)d_in[4];
    const float* Wv      = (const float*)d_in[5];
    const float* Wo      = (const float*)d_in[6];
    const float* bo      = (const float*)d_in[7];
    const float* n1s     = (const float*)d_in[8];
    const float* n1b     = (const float*)d_in[9];
    const float* n2s     = (const float*)d_in[10];
    const float* n2b     = (const float*)d_in[11];
    const float* W1      = (const float*)d_in[12];
    const float* b1      = (const float*)d_in[13];
    const float* W2      = (const float*)d_in[14];
    const float* b2      = (const float*)d_in[15];
    const float* fs      = (const float*)d_in[16];
    const float* fb      = (const float*)d_in[17];
    float* out = (float*)d_out;

    float *h, *qkv, *hf;
    __nv_bfloat16 *wqh, *wql, *woh, *wol, *w1h, *w1l, *w2h, *w2l;
    __nv_bfloat16 *xnh, *xnl, *ctxh, *ctxl, *ffh, *ffl;
    cudaGetSymbolAddress((void**)&h,    g_h);
    cudaGetSymbolAddress((void**)&qkv,  g_qkv);
    cudaGetSymbolAddress((void**)&hf,   g_hf);
    cudaGetSymbolAddress((void**)&wqh,  g_wqkv_h);
    cudaGetSymbolAddress((void**)&wql,  g_wqkv_l);
    cudaGetSymbolAddress((void**)&woh,  g_wo_h);
    cudaGetSymbolAddress((void**)&wol,  g_wo_l);
    cudaGetSymbolAddress((void**)&w1h,  g_w1_h);
    cudaGetSymbolAddress((void**)&w1l,  g_w1_l);
    cudaGetSymbolAddress((void**)&w2h,  g_w2_h);
    cudaGetSymbolAddress((void**)&w2l,  g_w2_l);
    cudaGetSymbolAddress((void**)&xnh,  g_xn_h);
    cudaGetSymbolAddress((void**)&xnl,  g_xn_l);
    cudaGetSymbolAddress((void**)&ctxh, g_ctx_h);
    cudaGetSymbolAddress((void**)&ctxl, g_ctx_l);
    cudaGetSymbolAddress((void**)&ffh,  g_ff_h);
    cudaGetSymbolAddress((void**)&ffl,  g_ff_l);

    const int ATTN_SMEM = (12288 + 64 * 65 + 3 * 64) * 4;  // 66560 B
    cudaFuncSetAttribute(attn_kernel, cudaFuncAttributeMaxDynamicSharedMemorySize, ATTN_SMEM);
    const int GEMM_SMEM = 2 * STGB;                        // 81920 B
    cudaFuncSetAttribute(gemm_bf16s_kernel, cudaFuncAttributeMaxDynamicSharedMemorySize, GEMM_SMEM);

    // weight split/pack (every call; deterministic)
    pack_qkv_kernel<<<(int)((size_t)LAYERS * QKV3 * D / 2048), 256>>>(Wq, Wk, Wv);
    split_w_kernel<<<(int)((size_t)LAYERS * D * D / 2048), 256>>>(Wo, woh, wol);
    split_w_kernel<<<(int)((size_t)LAYERS * DFF * D / 2048), 256>>>(W1, w1h, w1l);
    split_w_kernel<<<(int)((size_t)LAYERS * D * DFF / 2048), 256>>>(W2, w2h, w2l);

    embed_kernel<<<MROWS, 256>>>(x, W_emb, pos_emb);

    dim3 gQKV(QKV3 / 128, MROWS / 128);  // (24, 32)
    dim3 gD  (D / 128,    MROWS / 128);  // (8, 32)
    dim3 gF  (DFF / 128,  MROWS / 128);  // (32, 32)
    dim3 gA  (TLEN / 64, NH, BATCH);

    for (int l = 0; l < LAYERS; l++) {
        size_t wo  = (size_t)l * D * D;
        size_t wq3 = (size_t)l * QKV3 * D;
        size_t w1o = (size_t)l * DFF * D;
        size_t w2o = (size_t)l * D * DFF;
        ln_split_kernel<<<MROWS, 256>>>(h, xnh, xnl, n1s + l * D, n1b + l * D);
        gemm_bf16s_kernel<<<gQKV, 256, GEMM_SMEM>>>(xnh, xnl, wqh + wq3, wql + wq3,
            nullptr, nullptr, qkv, nullptr, nullptr, QKV3, D, 0);
        attn_kernel<<<gA, 128, ATTN_SMEM>>>(qkv, ctxh, ctxl);
        gemm_bf16s_kernel<<<gD, 256, GEMM_SMEM>>>(ctxh, ctxl, woh + wo, wol + wo,
            bo + l * D, h, h, nullptr, nullptr, D, D, 1);
        ln_split_kernel<<<MROWS, 256>>>(h, xnh, xnl, n2s + l * D, n2b + l * D);
        gemm_bf16s_kernel<<<gF, 256, GEMM_SMEM>>>(xnh, xnl, w1h + w1o, w1l + w1o,
            b1 + (size_t)l * DFF, nullptr, nullptr, ffh, ffl, DFF, D, 2);
        gemm_bf16s_kernel<<<gD, 256, GEMM_SMEM>>>(ffh, ffl, w2h + w2o, w2l + w2o,
            b2 + l * D, h, h, nullptr, nullptr, D, DFF, 1);
    }

    ln_kernel<<<BATCH, 256>>>(h, hf, fs, fb, TLEN - 1, TLEN);
    logits_kernel<<<(VOCAB + 7) / 8, 256>>>(hf, W_emb, out);
}

// round 7
// speedup vs baseline: 5.0213x; 1.5214x over previous
#include <cuda_runtime.h>
#include <cuda_bf16.h>
#include <math.h>
#include <stdint.h>

// ---------------- problem constants ----------------
#define LAYERS 8
#define D      1024
#define NH     16
#define HDIM   64
#define DFF    4096
#define VOCAB  50257
#define BATCH  2
#define TLEN   2048
#define MROWS  (BATCH*TLEN)   // 4096
#define EPS    1e-5f
#define QKV3   3072

// ---------------- scratch (static device globals; no allocs) ----------------
__device__ __nv_bfloat16 g_wqkv_h[LAYERS*(size_t)QKV3*D];
__device__ __nv_bfloat16 g_wqkv_l[LAYERS*(size_t)QKV3*D];
__device__ __nv_bfloat16 g_wo_h [LAYERS*(size_t)D*D];
__device__ __nv_bfloat16 g_wo_l [LAYERS*(size_t)D*D];
__device__ __nv_bfloat16 g_w1_h [LAYERS*(size_t)DFF*D];
__device__ __nv_bfloat16 g_w1_l [LAYERS*(size_t)DFF*D];
__device__ __nv_bfloat16 g_w2_h [LAYERS*(size_t)D*DFF];
__device__ __nv_bfloat16 g_w2_l [LAYERS*(size_t)D*DFF];
__device__ __nv_bfloat16 g_xn_h [MROWS*(size_t)D];
__device__ __nv_bfloat16 g_xn_l [MROWS*(size_t)D];
__device__ __nv_bfloat16 g_ctx_h[MROWS*(size_t)D];
__device__ __nv_bfloat16 g_ctx_l[MROWS*(size_t)D];
__device__ __nv_bfloat16 g_ff_h [MROWS*(size_t)DFF];
__device__ __nv_bfloat16 g_ff_l [MROWS*(size_t)DFF];
__device__ __nv_bfloat16 g_qkv3h[MROWS*(size_t)QKV3];
__device__ __nv_bfloat16 g_qkv3l[MROWS*(size_t)QKV3];
__device__ __nv_bfloat16 g_vth  [BATCH*NH*(size_t)HDIM*TLEN];
__device__ __nv_bfloat16 g_vtl  [BATCH*NH*(size_t)HDIM*TLEN];
__device__ float g_h  [MROWS*(size_t)D];
__device__ float g_hf [BATCH*D];

// ---------------- helpers ----------------
__device__ __forceinline__ void split2(float x, __nv_bfloat16& h, __nv_bfloat16& l) {
    h = __float2bfloat16(x);
    l = __float2bfloat16(x - __bfloat162float(h));
}

__device__ __forceinline__ void splitpack(float a, float b, uint32_t& hp, uint32_t& lp) {
    __nv_bfloat16 ha, la, hb, lb;
    split2(a, ha, la); split2(b, hb, lb);
    __nv_bfloat162 hv; hv.x = ha; hv.y = hb;
    __nv_bfloat162 lv; lv.x = la; lv.y = lb;
    hp = *(uint32_t*)&hv; lp = *(uint32_t*)&lv;
}

__device__ __forceinline__ float gelu_f(float x) {
    const float c = 0.7978845608028654f;
    float x3 = x * x * x;
    return 0.5f * x * (1.f + tanhf(c * (x + 0.044715f * x3)));
}

__device__ __forceinline__ void ldsm4(uint32_t* r, uint32_t addr) {
    asm volatile("ldmatrix.sync.aligned.m8n8.x4.shared.b16 {%0,%1,%2,%3}, [%4];"
                 : "=r"(r[0]), "=r"(r[1]), "=r"(r[2]), "=r"(r[3]) : "r"(addr));
}

__device__ __forceinline__ void mma_bf16(float* c, const uint32_t* a, const uint32_t* b) {
    asm volatile(
        "mma.sync.aligned.m16n8k16.row.col.f32.bf16.bf16.f32 "
        "{%0,%1,%2,%3}, {%4,%5,%6,%7}, {%8,%9}, {%0,%1,%2,%3};"
        : "+f"(c[0]), "+f"(c[1]), "+f"(c[2]), "+f"(c[3])
        : "r"(a[0]), "r"(a[1]), "r"(a[2]), "r"(a[3]), "r"(b[0]), "r"(b[1]));
}

__device__ __forceinline__ void cpa16(uint32_t s, const void* g) {
    asm volatile("cp.async.cg.shared.global [%0], [%1], 16;" :: "r"(s), "l"(g));
}
__device__ __forceinline__ void cp_commit() { asm volatile("cp.async.commit_group;"); }
__device__ __forceinline__ void cp_wait1()  { asm volatile("cp.async.wait_group 1;"); }
__device__ __forceinline__ void cp_wait0()  { asm volatile("cp.async.wait_group 0;"); }

// ---------------- weight split/pack kernels ----------------
__global__ void __launch_bounds__(256) split_w_kernel(const float* __restrict__ src,
    __nv_bfloat16* __restrict__ dh, __nv_bfloat16* __restrict__ dl)
{
    size_t i8 = ((size_t)blockIdx.x * 256 + threadIdx.x) * 8;
    float4 v0 = *(const float4*)(src + i8);
    float4 v1 = *(const float4*)(src + i8 + 4);
    __align__(16) __nv_bfloat16 h[8], l[8];
    split2(v0.x, h[0], l[0]); split2(v0.y, h[1], l[1]);
    split2(v0.z, h[2], l[2]); split2(v0.w, h[3], l[3]);
    split2(v1.x, h[4], l[4]); split2(v1.y, h[5], l[5]);
    split2(v1.z, h[6], l[6]); split2(v1.w, h[7], l[7]);
    *(uint4*)(dh + i8) = *(uint4*)h;
    *(uint4*)(dl + i8) = *(uint4*)l;
}

__global__ void __launch_bounds__(256) pack_qkv_kernel(const float* __restrict__ Wq,
    const float* __restrict__ Wk, const float* __restrict__ Wv)
{
    size_t i8 = ((size_t)blockIdx.x * 256 + threadIdx.x) * 8;
    size_t per_l = (size_t)QKV3 * D;
    int l = (int)(i8 / per_l);
    size_t rem = i8 % per_l;
    int n = (int)(rem / D);
    int k = (int)(rem % D);
    const float* src;
    if (n < D)          src = Wq + ((size_t)l * D + n) * D + k;
    else if (n < 2 * D) src = Wk + ((size_t)l * D + (n - D)) * D + k;
    else                src = Wv + ((size_t)l * D + (n - 2 * D)) * D + k;
    float4 v0 = *(const float4*)src;
    float4 v1 = *(const float4*)(src + 4);
    __align__(16) __nv_bfloat16 h[8], lo[8];
    split2(v0.x, h[0], lo[0]); split2(v0.y, h[1], lo[1]);
    split2(v0.z, h[2], lo[2]); split2(v0.w, h[3], lo[3]);
    split2(v1.x, h[4], lo[4]); split2(v1.y, h[5], lo[5]);
    split2(v1.z, h[6], lo[6]); split2(v1.w, h[7], lo[7]);
    *(uint4*)(g_wqkv_h + i8) = *(uint4*)h;
    *(uint4*)(g_wqkv_l + i8) = *(uint4*)lo;
}

// ---------------- embed ----------------
__global__ void __launch_bounds__(256) embed_kernel(const int* __restrict__ x,
    const float* __restrict__ wemb, const float* __restrict__ pos)
{
    int m = blockIdx.x;
    int tok = x[m];
    int t = m % TLEN;
    int c = threadIdx.x;
    float4 e = ((const float4*)(wemb + (size_t)tok * D))[c];
    float4 p = ((const float4*)(pos  + (size_t)t   * D))[c];
    e.x += p.x; e.y += p.y; e.z += p.z; e.w += p.w;
    ((float4*)(g_h + (size_t)m * D))[c] = e;
}

// ---------------- layernorm -> split bf16 planes ----------------
__global__ void __launch_bounds__(256) ln_split_kernel(const float* __restrict__ in,
    __nv_bfloat16* __restrict__ oh, __nv_bfloat16* __restrict__ ol,
    const float* __restrict__ sc, const float* __restrict__ sh)
{
    int row = blockIdx.x;
    int t = threadIdx.x;
    float4 v = ((const float4*)(in + (size_t)row * D))[t];
    float s  = v.x + v.y + v.z + v.w;
    float ss = v.x*v.x + v.y*v.y + v.z*v.z + v.w*v.w;
    #pragma unroll
    for (int o = 16; o; o >>= 1) {
        s  += __shfl_xor_sync(0xffffffffu, s,  o);
        ss += __shfl_xor_sync(0xffffffffu, ss, o);
    }
    __shared__ float shs[8], shss[8];
    if ((t & 31) == 0) { shs[t >> 5] = s; shss[t >> 5] = ss; }
    __syncthreads();
    float tot = 0.f, tots = 0.f;
    #pragma unroll
    for (int i = 0; i < 8; i++) { tot += shs[i]; tots += shss[i]; }
    float mean = tot * (1.f / (float)D);
    float var  = (tots - (float)D * mean * mean) * (1.f / (float)(D - 1));
    var = fmaxf(var, 0.f);
    float inv = 1.f / (sqrtf(var) + EPS);
    float4 scv = ((const float4*)sc)[t];
    float4 shv = ((const float4*)sh)[t];
    float r0 = scv.x * (v.x - mean) * inv + shv.x;
    float r1 = scv.y * (v.y - mean) * inv + shv.y;
    float r2 = scv.z * (v.z - mean) * inv + shv.z;
    float r3 = scv.w * (v.w - mean) * inv + shv.w;
    __align__(8) __nv_bfloat16 h[4], l[4];
    split2(r0, h[0], l[0]); split2(r1, h[1], l[1]);
    split2(r2, h[2], l[2]); split2(r3, h[3], l[3]);
    *(uint2*)(oh + (size_t)row * D + t * 4) = *(uint2*)h;
    *(uint2*)(ol + (size_t)row * D + t * 4) = *(uint2*)l;
}

// ---------------- layernorm fp32 out (final) ----------------
__global__ void __launch_bounds__(256) ln_kernel(const float* __restrict__ in,
    float* __restrict__ out, const float* __restrict__ sc, const float* __restrict__ sh,
    int row0, int rstride)
{
    int rin = row0 + blockIdx.x * rstride;
    int t = threadIdx.x;
    float4 v = ((const float4*)(in + (size_t)rin * D))[t];
    float s  = v.x + v.y + v.z + v.w;
    float ss = v.x*v.x + v.y*v.y + v.z*v.z + v.w*v.w;
    #pragma unroll
    for (int o = 16; o; o >>= 1) {
        s  += __shfl_xor_sync(0xffffffffu, s,  o);
        ss += __shfl_xor_sync(0xffffffffu, ss, o);
    }
    __shared__ float shs[8], shss[8];
    if ((t & 31) == 0) { shs[t >> 5] = s; shss[t >> 5] = ss; }
    __syncthreads();
    float tot = 0.f, tots = 0.f;
    #pragma unroll
    for (int i = 0; i < 8; i++) { tot += shs[i]; tots += shss[i]; }
    float mean = tot * (1.f / (float)D);
    float var  = (tots - (float)D * mean * mean) * (1.f / (float)(D - 1));
    var = fmaxf(var, 0.f);
    float inv = 1.f / (sqrtf(var) + EPS);
    float4 scv = ((const float4*)sc)[t];
    float4 shv = ((const float4*)sh)[t];
    float4 r;
    r.x = scv.x * (v.x - mean) * inv + shv.x;
    r.y = scv.y * (v.y - mean) * inv + shv.y;
    r.z = scv.z * (v.z - mean) * inv + shv.z;
    r.w = scv.w * (v.w - mean) * inv + shv.w;
    ((float4*)(out + (size_t)blockIdx.x * D))[t] = r;
}

// ---------------- split-bf16 tensor-core GEMM ----------------
// mode 0: store fp32 ; 1: out = res + acc + bias (fp32)
// mode 2: oh/ol = split(gelu(acc+bias)) ; mode 3: oh/ol = split(acc)
#define SROW  40
#define PLANE (128*SROW)
#define PLB   (PLANE*2)
#define STGB  (4*PLB)

__global__ void __launch_bounds__(256, 2) gemm_bf16s_kernel(
    const __nv_bfloat16* __restrict__ Ah, const __nv_bfloat16* __restrict__ Al,
    const __nv_bfloat16* __restrict__ Wh, const __nv_bfloat16* __restrict__ Wl,
    const float* __restrict__ bias, const float* __restrict__ res,
    float* __restrict__ out,
    __nv_bfloat16* __restrict__ oh, __nv_bfloat16* __restrict__ ol,
    int N, int K, int mode)
{
    extern __shared__ __align__(16) char smraw[];
    uint32_t smb = (uint32_t)__cvta_generic_to_shared(smraw);

    int tid = threadIdx.x, lane = tid & 31, warp = tid >> 5;
    int warp_m = warp >> 1;
    int warp_n = warp & 1;
    int m0 = blockIdx.y * 128;
    int n0 = blockIdx.x * 128;

    int lr = tid >> 2;
    int lc = (tid & 3) * 8;
    const __nv_bfloat16* gAh = Ah + (size_t)(m0 + lr) * K + lc;
    const __nv_bfloat16* gAl = Al + (size_t)(m0 + lr) * K + lc;
    const __nv_bfloat16* gBh = Wh + (size_t)(n0 + lr) * K + lc;
    const __nv_bfloat16* gBl = Wl + (size_t)(n0 + lr) * K + lc;
    size_t rstep = (size_t)64 * K;
    uint32_t sdst = smb + (uint32_t)(lr * SROW + lc) * 2;

    uint32_t a_off = (uint32_t)((warp_m * 32 + (lane & 15)) * SROW) * 2 + (lane >> 4) * 16;
    uint32_t b_off = (uint32_t)((warp_n * 64 + ((lane >> 4) & 1) * 8 + (lane & 7)) * SROW) * 2
                   + ((lane >> 3) & 1) * 16;

    float c[2][8][4];
    #pragma unroll
    for (int mt = 0; mt < 2; mt++)
        #pragma unroll
        for (int nt = 0; nt < 8; nt++)
            #pragma unroll
            for (int i = 0; i < 4; i++) c[mt][nt][i] = 0.f;

    int nk = K / 32;

    {
        uint32_t sb = sdst;
        cpa16(sb,             gAh);          cpa16(sb + 64 * SROW * 2,             gAh + rstep);
        cpa16(sb + PLB,       gAl);          cpa16(sb + PLB + 64 * SROW * 2,       gAl + rstep);
        cpa16(sb + 2 * PLB,   gBh);          cpa16(sb + 2 * PLB + 64 * SROW * 2,   gBh + rstep);
        cpa16(sb + 3 * PLB,   gBl);          cpa16(sb + 3 * PLB + 64 * SROW * 2,   gBl + rstep);
        cp_commit();
    }

    for (int kt = 0; kt < nk; kt++) {
        int buf = kt & 1;
        if (kt + 1 < nk) {
            uint32_t sb = sdst + (uint32_t)((buf ^ 1) * STGB);
            int ko = (kt + 1) * 32;
            cpa16(sb,           gAh + ko);        cpa16(sb + 64 * SROW * 2,           gAh + ko + rstep);
            cpa16(sb + PLB,     gAl + ko);        cpa16(sb + PLB + 64 * SROW * 2,     gAl + ko + rstep);
            cpa16(sb + 2 * PLB, gBh + ko);        cpa16(sb + 2 * PLB + 64 * SROW * 2, gBh + ko + rstep);
            cpa16(sb + 3 * PLB, gBl + ko);        cpa16(sb + 3 * PLB + 64 * SROW * 2, gBl + ko + rstep);
            cp_commit();
            cp_wait1();
        } else {
            cp_wait0();
        }
        __syncthreads();

        uint32_t base = smb + (uint32_t)(buf * STGB);
        #pragma unroll
        for (int s = 0; s < 2; s++) {
            uint32_t ah[2][4], al[2][4];
            ldsm4(ah[0], base + a_off + s * 32);
            ldsm4(ah[1], base + a_off + 16 * SROW * 2 + s * 32);
            ldsm4(al[0], base + PLB + a_off + s * 32);
            ldsm4(al[1], base + PLB + a_off + 16 * SROW * 2 + s * 32);
            #pragma unroll
            for (int p2 = 0; p2 < 4; p2++) {
                uint32_t bh[4];
                ldsm4(bh, base + 2 * PLB + b_off + p2 * (16 * SROW * 2) + s * 32);
                #pragma unroll
                for (int mt = 0; mt < 2; mt++) {
                    mma_bf16(c[mt][2 * p2],     ah[mt], &bh[0]);
                    mma_bf16(c[mt][2 * p2 + 1], ah[mt], &bh[2]);
                    mma_bf16(c[mt][2 * p2],     al[mt], &bh[0]);
                    mma_bf16(c[mt][2 * p2 + 1], al[mt], &bh[2]);
                }
            }
            #pragma unroll
            for (int p2 = 0; p2 < 4; p2++) {
                uint32_t bl[4];
                ldsm4(bl, base + 3 * PLB + b_off + p2 * (16 * SROW * 2) + s * 32);
                #pragma unroll
                for (int mt = 0; mt < 2; mt++) {
                    mma_bf16(c[mt][2 * p2],     ah[mt], &bl[0]);
                    mma_bf16(c[mt][2 * p2 + 1], ah[mt], &bl[2]);
                }
            }
        }
        __syncthreads();
    }

    int rbase = m0 + warp_m * 32 + (lane >> 2);
    int cb0   = n0 + warp_n * 64 + (lane & 3) * 2;
    #pragma unroll
    for (int mt = 0; mt < 2; mt++) {
        #pragma unroll
        for (int nt = 0; nt < 8; nt++) {
            int col = cb0 + nt * 8;
            #pragma unroll
            for (int half = 0; half < 2; half++) {
                int row = rbase + mt * 16 + half * 8;
                float vx = c[mt][nt][half * 2];
                float vy = c[mt][nt][half * 2 + 1];
                size_t off = (size_t)row * N + col;
                if (mode == 0) {
                    *(float2*)(out + off) = make_float2(vx, vy);
                } else if (mode == 1) {
                    float2 rv = *(const float2*)(res + off);
                    vx += bias[col] + rv.x;
                    vy += bias[col + 1] + rv.y;
                    *(float2*)(out + off) = make_float2(vx, vy);
                } else {
                    if (mode == 2) {
                        vx = gelu_f(vx + bias[col]);
                        vy = gelu_f(vy + bias[col + 1]);
                    }
                    uint32_t hp, lp;
                    splitpack(vx, vy, hp, lp);
                    *(uint32_t*)(oh + off) = hp;
                    *(uint32_t*)(ol + off) = lp;
                }
            }
        }
    }
}

// ---------------- V transpose: qkv v-part -> vt[bh*64+d][t] ----------------
__global__ void __launch_bounds__(256) vtrans_kernel(
    const __nv_bfloat16* __restrict__ qh, const __nv_bfloat16* __restrict__ ql,
    __nv_bfloat16* __restrict__ vth, __nv_bfloat16* __restrict__ vtl)
{
    __shared__ __nv_bfloat16 th[32][33], tl[32][33];
    int bh = blockIdx.z; int b = bh >> 4, hh = bh & 15;
    int t0 = blockIdx.x * 32, d0 = blockIdx.y * 32;
    int tx = threadIdx.x & 31, ty = threadIdx.x >> 5;
    #pragma unroll
    for (int i = 0; i < 4; i++) {
        int r = ty + i * 8;
        size_t off = (size_t)(b * TLEN + t0 + r) * QKV3 + 2 * D + hh * HDIM + d0 + tx;
        th[r][tx] = qh[off];
        tl[r][tx] = ql[off];
    }
    __syncthreads();
    #pragma unroll
    for (int i = 0; i < 4; i++) {
        int r = ty + i * 8;
        size_t off = (size_t)(bh * HDIM + d0 + r) * TLEN + t0 + tx;
        vth[off] = th[tx][r];
        vtl[off] = tl[tx][r];
    }
}

// ---------------- tensor-core flash attention (split-bf16) ----------------
// BQ=128 (8 warps x m16), BK=64. grid (T/128, NH, BATCH), 256 threads.
#define ASTR 72
#define QH_OFF 0
#define QL_OFF (128*ASTR)
#define KH_OFF (2*128*ASTR)
#define KL_OFF (KH_OFF + 64*ASTR)
#define VH_OFF (KL_OFF + 64*ASTR)
#define VL_OFF (VH_OFF + 64*ASTR)
#define ATT_SMEM ((VL_OFF + 64*ASTR)*2)   // 73728 bytes

__global__ void __launch_bounds__(256) attn_mma_kernel(
    const __nv_bfloat16* __restrict__ qkvh, const __nv_bfloat16* __restrict__ qkvl,
    const __nv_bfloat16* __restrict__ vth, const __nv_bfloat16* __restrict__ vtl,
    __nv_bfloat16* __restrict__ ctxh, __nv_bfloat16* __restrict__ ctxl)
{
    extern __shared__ __align__(16) __nv_bfloat16 sma[];
    uint32_t smb = (uint32_t)__cvta_generic_to_shared(sma);
    int b = blockIdx.z, hh = blockIdx.y;
    int q0 = blockIdx.x * 128;
    int tid = threadIdx.x, lane = tid & 31, w = tid >> 5;
    int bh = b * NH + hh;

    // Q tiles (hi+lo) via cp.async, loaded once
    {
        int row = tid >> 1, half = (tid & 1) * 32;
        const __nv_bfloat16* gqh = qkvh + (size_t)(b * TLEN + q0 + row) * QKV3 + hh * HDIM + half;
        const __nv_bfloat16* gql = qkvl + (size_t)(b * TLEN + q0 + row) * QKV3 + hh * HDIM + half;
        uint32_t s0 = smb + (uint32_t)(QH_OFF + row * ASTR + half) * 2;
        uint32_t s1 = smb + (uint32_t)(QL_OFF + row * ASTR + half) * 2;
        #pragma unroll
        for (int j = 0; j < 4; j++) {
            cpa16(s0 + j * 16, gqh + j * 8);
            cpa16(s1 + j * 16, gql + j * 8);
        }
        cp_commit();
    }

    uint32_t qa_off = (uint32_t)((w * 16 + (lane & 15)) * ASTR) * 2 + (lane >> 4) * 16;
    uint32_t nb_off = (uint32_t)(((((lane >> 4) & 1) * 8) + (lane & 7)) * ASTR) * 2
                    + ((lane >> 3) & 1) * 16;

    float o[8][4];
    #pragma unroll
    for (int j = 0; j < 8; j++)
        #pragma unroll
        for (int i = 0; i < 4; i++) o[j][i] = 0.f;
    float m0 = -1e30f, m1 = -1e30f, l0 = 0.f, l1 = 0.f;
    int r0 = lane >> 2;
    int qi0 = q0 + w * 16 + r0, qi1 = qi0 + 8;

    int nkb = (blockIdx.x + 1) * 2;
    int krow = tid >> 2, kq = (tid & 3) * 16;

    for (int kb = 0; kb < nkb; kb++) {
        int k0 = kb * 64;
        __syncthreads();
        {
            const __nv_bfloat16* gkh = qkvh + (size_t)(b * TLEN + k0 + krow) * QKV3 + D + hh * HDIM + kq;
            const __nv_bfloat16* gkl = qkvl + (size_t)(b * TLEN + k0 + krow) * QKV3 + D + hh * HDIM + kq;
            const __nv_bfloat16* gvh = vth + (size_t)(bh * HDIM + krow) * TLEN + k0 + kq;
            const __nv_bfloat16* gvl = vtl + (size_t)(bh * HDIM + krow) * TLEN + k0 + kq;
            uint32_t skh = smb + (uint32_t)(KH_OFF + krow * ASTR + kq) * 2;
            uint32_t skl = smb + (uint32_t)(KL_OFF + krow * ASTR + kq) * 2;
            uint32_t svh = smb + (uint32_t)(VH_OFF + krow * ASTR + kq) * 2;
            uint32_t svl = smb + (uint32_t)(VL_OFF + krow * ASTR + kq) * 2;
            cpa16(skh, gkh); cpa16(skh + 16, gkh + 8);
            cpa16(skl, gkl); cpa16(skl + 16, gkl + 8);
            cpa16(svh, gvh); cpa16(svh + 16, gvh + 8);
            cpa16(svl, gvl); cpa16(svl + 16, gvl + 8);
            cp_commit();
        }
        cp_wait0();
        __syncthreads();

        bool active = (k0 <= q0 + w * 16 + 15);
        if (active) {
            float s[8][4];
            #pragma unroll
            for (int j = 0; j < 8; j++)
                #pragma unroll
                for (int i = 0; i < 4; i++) s[j][i] = 0.f;

            #pragma unroll
            for (int ks = 0; ks < 4; ks++) {
                uint32_t ah[4], al[4];
                ldsm4(ah, smb + QH_OFF * 2 + qa_off + ks * 32);
                ldsm4(al, smb + QL_OFF * 2 + qa_off + ks * 32);
                #pragma unroll
                for (int p2 = 0; p2 < 4; p2++) {
                    uint32_t bh4[4], bl4[4];
                    ldsm4(bh4, smb + KH_OFF * 2 + nb_off + p2 * (16 * ASTR * 2) + ks * 32);
                    mma_bf16(s[2 * p2],     ah, &bh4[0]);
                    mma_bf16(s[2 * p2 + 1], ah, &bh4[2]);
                    mma_bf16(s[2 * p2],     al, &bh4[0]);
                    mma_bf16(s[2 * p2 + 1], al, &bh4[2]);
                    ldsm4(bl4, smb + KL_OFF * 2 + nb_off + p2 * (16 * ASTR * 2) + ks * 32);
                    mma_bf16(s[2 * p2],     ah, &bl4[0]);
                    mma_bf16(s[2 * p2 + 1], ah, &bl4[2]);
                }
            }

            // scale + causal mask
            #pragma unroll
            for (int j = 0; j < 8; j++) {
                int c0 = k0 + j * 8 + (lane & 3) * 2;
                s[j][0] = (c0     > qi0) ? -1e30f : s[j][0] * 0.125f;
                s[j][1] = (c0 + 1 > qi0) ? -1e30f : s[j][1] * 0.125f;
                s[j][2] = (c0     > qi1) ? -1e30f : s[j][2] * 0.125f;
                s[j][3] = (c0 + 1 > qi1) ? -1e30f : s[j][3] * 0.125f;
            }
            // row max (4 lanes share a row)
            float mx0 = -1e30f, mx1 = -1e30f;
            #pragma unroll
            for (int j = 0; j < 8; j++) {
                mx0 = fmaxf(mx0, fmaxf(s[j][0], s[j][1]));
                mx1 = fmaxf(mx1, fmaxf(s[j][2], s[j][3]));
            }
            mx0 = fmaxf(mx0, __shfl_xor_sync(0xffffffffu, mx0, 1));
            mx0 = fmaxf(mx0, __shfl_xor_sync(0xffffffffu, mx0, 2));
            mx1 = fmaxf(mx1, __shfl_xor_sync(0xffffffffu, mx1, 1));
            mx1 = fmaxf(mx1, __shfl_xor_sync(0xffffffffu, mx1, 2));
            float mn0 = fmaxf(m0, mx0), mn1 = fmaxf(m1, mx1);
            float sf0 = __expf(m0 - mn0), sf1 = __expf(m1 - mn1);
            m0 = mn0; m1 = mn1;
            float sum0 = 0.f, sum1 = 0.f;
            #pragma unroll
            for (int j = 0; j < 8; j++) {
                s[j][0] = __expf(s[j][0] - mn0);
                s[j][1] = __expf(s[j][1] - mn0);
                s[j][2] = __expf(s[j][2] - mn1);
                s[j][3] = __expf(s[j][3] - mn1);
                sum0 += s[j][0] + s[j][1];
                sum1 += s[j][2] + s[j][3];
            }
            sum0 += __shfl_xor_sync(0xffffffffu, sum0, 1);
            sum0 += __shfl_xor_sync(0xffffffffu, sum0, 2);
            sum1 += __shfl_xor_sync(0xffffffffu, sum1, 1);
            sum1 += __shfl_xor_sync(0xffffffffu, sum1, 2);
            l0 = l0 * sf0 + sum0;
            l1 = l1 * sf1 + sum1;
            #pragma unroll
            for (int j = 0; j < 8; j++) {
                o[j][0] *= sf0; o[j][1] *= sf0;
                o[j][2] *= sf1; o[j][3] *= sf1;
            }
            // P (split) @ V (split)
            #pragma unroll
            for (int t = 0; t < 4; t++) {
                uint32_t ph4[4], pl4[4];
                splitpack(s[2 * t][0],     s[2 * t][1],     ph4[0], pl4[0]);
                splitpack(s[2 * t][2],     s[2 * t][3],     ph4[1], pl4[1]);
                splitpack(s[2 * t + 1][0], s[2 * t + 1][1], ph4[2], pl4[2]);
                splitpack(s[2 * t + 1][2], s[2 * t + 1][3], ph4[3], pl4[3]);
                #pragma unroll
                for (int p2 = 0; p2 < 4; p2++) {
                    uint32_t vh4[4], vl4[4];
                    ldsm4(vh4, smb + VH_OFF * 2 + nb_off + p2 * (16 * ASTR * 2) + t * 32);
                    mma_bf16(o[2 * p2],     ph4, &vh4[0]);
                    mma_bf16(o[2 * p2 + 1], ph4, &vh4[2]);
                    mma_bf16(o[2 * p2],     pl4, &vh4[0]);
                    mma_bf16(o[2 * p2 + 1], pl4, &vh4[2]);
                    ldsm4(vl4, smb + VL_OFF * 2 + nb_off + p2 * (16 * ASTR * 2) + t * 32);
                    mma_bf16(o[2 * p2],     ph4, &vl4[0]);
                    mma_bf16(o[2 * p2 + 1], ph4, &vl4[2]);
                }
            }
        }
    }

    float il0 = 1.f / l0, il1 = 1.f / l1;
    #pragma unroll
    for (int j = 0; j < 8; j++) {
        int col = hh * HDIM + j * 8 + (lane & 3) * 2;
        size_t off0 = (size_t)(b * TLEN + qi0) * D + col;
        size_t off1 = (size_t)(b * TLEN + qi1) * D + col;
        uint32_t hp, lp;
        splitpack(o[j][0] * il0, o[j][1] * il0, hp, lp);
        *(uint32_t*)(ctxh + off0) = hp;
        *(uint32_t*)(ctxl + off0) = lp;
        splitpack(o[j][2] * il1, o[j][3] * il1, hp, lp);
        *(uint32_t*)(ctxh + off1) = hp;
        *(uint32_t*)(ctxl + off1) = lp;
    }
}

// ---------------- last-token logits ----------------
__global__ void __launch_bounds__(256) logits_kernel(
    const float* __restrict__ hf, const float* __restrict__ wemb, float* __restrict__ out)
{
    __shared__ float h0[D], h1[D];
    int t = threadIdx.x;
    ((float4*)h0)[t] = ((const float4*)hf)[t];
    ((float4*)h1)[t] = ((const float4*)(hf + D))[t];
    __syncthreads();
    int warp = t >> 5, lane = t & 31;
    int n = blockIdx.x * 8 + warp;
    if (n >= VOCAB) return;
    const float4* w = (const float4*)(wemb + (size_t)n * D);
    float a0 = 0.f, a1 = 0.f;
    #pragma unroll
    for (int i = lane; i < D / 4; i += 32) {
        float4 wv = w[i];
        float4 x0 = ((float4*)h0)[i];
        float4 x1 = ((float4*)h1)[i];
        a0 += wv.x * x0.x + wv.y * x0.y + wv.z * x0.z + wv.w * x0.w;
        a1 += wv.x * x1.x + wv.y * x1.y + wv.z * x1.z + wv.w * x1.w;
    }
    #pragma unroll
    for (int o = 16; o; o >>= 1) {
        a0 += __shfl_xor_sync(0xffffffffu, a0, o);
        a1 += __shfl_xor_sync(0xffffffffu, a1, o);
    }
    if (lane == 0) {
        out[n] = a0;
        out[VOCAB + n] = a1;
    }
}

// ---------------- launch ----------------
extern "C" void kernel_launch(void* const* d_in, const int* in_sizes, int n_in,
                              void* d_out, int out_size)
{
    const int*   x       = (const int*)  d_in[0];
    const float* W_emb   = (const float*)d_in[1];
    const float* pos_emb = (const float*)d_in[2];
    const float* Wq      = (const float*)d_in[3];
    const float* Wk      = (const float*)d_in[4];
    const float* Wv      = (const float*)d_in[5];
    const float* Wo      = (const float*)d_in[6];
    const float* bo      = (const float*)d_in[7];
    const float* n1s     = (const float*)d_in[8];
    const float* n1b     = (const float*)d_in[9];
    const float* n2s     = (const float*)d_in[10];
    const float* n2b     = (const float*)d_in[11];
    const float* W1      = (const float*)d_in[12];
    const float* b1      = (const float*)d_in[13];
    const float* W2      = (const float*)d_in[14];
    const float* b2      = (const float*)d_in[15];
    const float* fs      = (const float*)d_in[16];
    const float* fb      = (const float*)d_in[17];
    float* out = (float*)d_out;

    float *h, *hf;
    __nv_bfloat16 *wqh, *wql, *woh, *wol, *w1h, *w1l, *w2h, *w2l;
    __nv_bfloat16 *xnh, *xnl, *ctxh, *ctxl, *ffh, *ffl;
    __nv_bfloat16 *qkvh, *qkvl, *vth, *vtl;
    cudaGetSymbolAddress((void**)&h,    g_h);
    cudaGetSymbolAddress((void**)&hf,   g_hf);
    cudaGetSymbolAddress((void**)&wqh,  g_wqkv_h);
    cudaGetSymbolAddress((void**)&wql,  g_wqkv_l);
    cudaGetSymbolAddress((void**)&woh,  g_wo_h);
    cudaGetSymbolAddress((void**)&wol,  g_wo_l);
    cudaGetSymbolAddress((void**)&w1h,  g_w1_h);
    cudaGetSymbolAddress((void**)&w1l,  g_w1_l);
    cudaGetSymbolAddress((void**)&w2h,  g_w2_h);
    cudaGetSymbolAddress((void**)&w2l,  g_w2_l);
    cudaGetSymbolAddress((void**)&xnh,  g_xn_h);
    cudaGetSymbolAddress((void**)&xnl,  g_xn_l);
    cudaGetSymbolAddress((void**)&ctxh, g_ctx_h);
    cudaGetSymbolAddress((void**)&ctxl, g_ctx_l);
    cudaGetSymbolAddress((void**)&ffh,  g_ff_h);
    cudaGetSymbolAddress((void**)&ffl,  g_ff_l);
    cudaGetSymbolAddress((void**)&qkvh, g_qkv3h);
    cudaGetSymbolAddress((void**)&qkvl, g_qkv3l);
    cudaGetSymbolAddress((void**)&vth,  g_vth);
    cudaGetSymbolAddress((void**)&vtl,  g_vtl);

    const int GEMM_SMEM = 2 * STGB;
    cudaFuncSetAttribute(gemm_bf16s_kernel, cudaFuncAttributeMaxDynamicSharedMemorySize, GEMM_SMEM);
    cudaFuncSetAttribute(attn_mma_kernel, cudaFuncAttributeMaxDynamicSharedMemorySize, ATT_SMEM);

    pack_qkv_kernel<<<(int)((size_t)LAYERS * QKV3 * D / 2048), 256>>>(Wq, Wk, Wv);
    split_w_kernel<<<(int)((size_t)LAYERS * D * D / 2048), 256>>>(Wo, woh, wol);
    split_w_kernel<<<(int)((size_t)LAYERS * DFF * D / 2048), 256>>>(W1, w1h, w1l);
    split_w_kernel<<<(int)((size_t)LAYERS * D * DFF / 2048), 256>>>(W2, w2h, w2l);

    embed_kernel<<<MROWS, 256>>>(x, W_emb, pos_emb);

    dim3 gQKV(QKV3 / 128, MROWS / 128);  // (24, 32)
    dim3 gD  (D / 128,    MROWS / 128);  // (8, 32)
    dim3 gF  (DFF / 128,  MROWS / 128);  // (32, 32)
    dim3 gVT (TLEN / 32, HDIM / 32, BATCH * NH);
    dim3 gA  (TLEN / 128, NH, BATCH);

    for (int l = 0; l < LAYERS; l++) {
        size_t wo  = (size_t)l * D * D;
        size_t wq3 = (size_t)l * QKV3 * D;
        size_t w1o = (size_t)l * DFF * D;
        size_t w2o = (size_t)l * D * DFF;
        ln_split_kernel<<<MROWS, 256>>>(h, xnh, xnl, n1s + l * D, n1b + l * D);
        gemm_bf16s_kernel<<<gQKV, 256, GEMM_SMEM>>>(xnh, xnl, wqh + wq3, wql + wq3,
            nullptr, nullptr, nullptr, qkvh, qkvl, QKV3, D, 3);
        vtrans_kernel<<<gVT, 256>>>(qkvh, qkvl, vth, vtl);
        attn_mma_kernel<<<gA, 256, ATT_SMEM>>>(qkvh, qkvl, vth, vtl, ctxh, ctxl);
        gemm_bf16s_kernel<<<gD, 256, GEMM_SMEM>>>(ctxh, ctxl, woh + wo, wol + wo,
            bo + l * D, h, h, nullptr, nullptr, D, D, 1);
        ln_split_kernel<<<MROWS, 256>>>(h, xnh, xnl, n2s + l * D, n2b + l * D);
        gemm_bf16s_kernel<<<gF, 256, GEMM_SMEM>>>(xnh, xnl, w1h + w1o, w1l + w1o,
            b1 + (size_t)l * DFF, nullptr, nullptr, ffh, ffl, DFF, D, 2);
        gemm_bf16s_kernel<<<gD, 256, GEMM_SMEM>>>(ffh, ffl, w2h + w2o, w2l + w2o,
            b2 + l * D, h, h, nullptr, nullptr, D, DFF, 1);
    }

    ln_kernel<<<BATCH, 256>>>(h, hf, fs, fb, TLEN - 1, TLEN);
    logits_kernel<<<(VOCAB + 7) / 8, 256>>>(hf, W_emb, out);
}